// round 5
// baseline (speedup 1.0000x reference)
#include <cuda_runtime.h>
#include <math.h>

#define BATCH 2
#define S_LEN 2048
#define HID   4096
#define NH    32
#define NKV   8
#define HD    128
#define QKVN  6144          // Q 4096 | K 1024 | V 1024
#define VOFF  5120          // Q_SIZE + KV_SIZE

// ---------------- scratch (no allocation allowed -> device globals) ----------
__device__ float g_qkv [BATCH * S_LEN * QKVN];      // qkv projection output
__device__ float g_qT  [BATCH * NH  * HD * S_LEN];  // rope'd Q, layout [b][h][d][s]
__device__ float g_kT  [BATCH * NKV * HD * S_LEN];  // rope'd K, layout [b][kh][d][s]
__device__ float g_attn[BATCH * S_LEN * HID];       // attention output (pre w_o)
__device__ float g_invfreq[64];

// ---------------- inv_freq table (fp32, exact enough: <=1ulp) -----------------
__global__ void init_invfreq_kernel() {
    int i = threadIdx.x;
    if (i < 64) {
        // 10000^(-2i/128) = exp2(-(2i/128) * log2(10000))
        const float LOG2_10000 = 13.28771237954945f;
        g_invfreq[i] = exp2f(-((float)(2 * i) / 128.0f) * LOG2_10000);
    }
}

// ---------------- SGEMM: C[MxN] = A[MxK] @ B[KxN], row-major ------------------
// 128x128 block tile, BK=16, 256 threads, 8x8 per-thread micro tile.
// M,N,K all multiples of 128/16 here -> no bounds checks.
__global__ void __launch_bounds__(256) sgemm_kernel(
    const float* __restrict__ A, const float* __restrict__ B,
    float* __restrict__ C, int N, int K)
{
    __shared__ float As[16][128];   // transposed A tile: As[k][m]
    __shared__ float Bs[16][128];   // Bs[k][n]

    const int t  = threadIdx.x;
    const int tx = t & 15;
    const int ty = t >> 4;

    const float* Ab = A + (size_t)blockIdx.y * 128 * K;
    const float* Bb = B + (size_t)blockIdx.x * 128;

    float acc[8][8];
#pragma unroll
    for (int i = 0; i < 8; i++)
#pragma unroll
        for (int j = 0; j < 8; j++) acc[i][j] = 0.f;

    for (int k0 = 0; k0 < K; k0 += 16) {
#pragma unroll
        for (int u = 0; u < 2; u++) {
            int id = t + u * 256;
            // A tile: 128 rows x 4 float4 cols
            int ar = id >> 2, ac = id & 3;
            float4 av = *(const float4*)(Ab + (size_t)ar * K + k0 + ac * 4);
            As[ac * 4 + 0][ar] = av.x;
            As[ac * 4 + 1][ar] = av.y;
            As[ac * 4 + 2][ar] = av.z;
            As[ac * 4 + 3][ar] = av.w;
            // B tile: 16 rows x 32 float4 cols
            int br = id >> 5, bc = id & 31;
            *(float4*)(&Bs[br][bc * 4]) =
                *(const float4*)(Bb + (size_t)(k0 + br) * N + bc * 4);
        }
        __syncthreads();

#pragma unroll
        for (int kk = 0; kk < 16; kk++) {
            float a[8], b[8];
            *(float4*)&a[0] = *(const float4*)&As[kk][ty * 8];
            *(float4*)&a[4] = *(const float4*)&As[kk][ty * 8 + 4];
            *(float4*)&b[0] = *(const float4*)&Bs[kk][tx * 8];
            *(float4*)&b[4] = *(const float4*)&Bs[kk][tx * 8 + 4];
#pragma unroll
            for (int i = 0; i < 8; i++)
#pragma unroll
                for (int j = 0; j < 8; j++)
                    acc[i][j] = fmaf(a[i], b[j], acc[i][j]);
        }
        __syncthreads();
    }

    float* Cb = C + (size_t)(blockIdx.y * 128 + ty * 8) * N + blockIdx.x * 128 + tx * 8;
#pragma unroll
    for (int i = 0; i < 8; i++) {
        float4 r0 = make_float4(acc[i][0], acc[i][1], acc[i][2], acc[i][3]);
        float4 r1 = make_float4(acc[i][4], acc[i][5], acc[i][6], acc[i][7]);
        *(float4*)(Cb + (size_t)i * N)     = r0;
        *(float4*)(Cb + (size_t)i * N + 4) = r1;
    }
}

// ---------------- RoPE (NeoX) + transpose into [b][head][d][s] ----------------
// One thread per (b, head-slot, s, i<64): produces rotated pair (d=i, d=i+64).
// head-slot 0..31 = Q heads -> g_qT ; 32..39 = KV heads -> g_kT.
__global__ void rope_kernel(const float* __restrict__ qkv,
                            const int*   __restrict__ positions)
{
    int idx = blockIdx.x * 256 + threadIdx.x;
    int i  = idx & 63;
    int s  = (idx >> 6) & (S_LEN - 1);
    int r  = idx >> 17;          // b*40 + hh
    int hh = r % 40;
    int b  = r / 40;

    float pos = (float)positions[b * S_LEN + s];
    float ang = pos * g_invfreq[i];
    float sn, cs;
    sincosf(ang, &sn, &cs);      // accurate variant (large-arg reduction)

    if (hh < 32) {
        const float* src = qkv + ((size_t)(b * S_LEN + s)) * QKVN + hh * HD;
        float x1 = src[i], x2 = src[i + 64];
        float* dst = g_qT + ((size_t)(b * NH + hh) * HD) * S_LEN;
        dst[(size_t)i * S_LEN + s]        = x1 * cs - x2 * sn;
        dst[(size_t)(i + 64) * S_LEN + s] = x2 * cs + x1 * sn;
    } else {
        int kh = hh - 32;
        const float* src = qkv + ((size_t)(b * S_LEN + s)) * QKVN + HID + kh * HD;
        float x1 = src[i], x2 = src[i + 64];
        float* dst = g_kT + ((size_t)(b * NKV + kh) * HD) * S_LEN;
        dst[(size_t)i * S_LEN + s]        = x1 * cs - x2 * sn;
        dst[(size_t)(i + 64) * S_LEN + s] = x2 * cs + x1 * sn;
    }
}

// ---------------- Flash attention, causal, GQA (rep=4) ------------------------
// Block = (q-tile of 64, head, batch). 256 threads as 16x16.
// Score phase:  thread (ty,tx) -> rows i0=ty*4..+4, cols j0=tx*4..+4
// PV phase:     thread (ty,tx) -> rows i0=ty*4..+4, cols d0=tx*8..+8
// smem: Qt[128][68], Kt[128][68] (d-major, pre-transposed in gmem),
//       Pt[64][68] (transposed probs), Vs[64][128].
#define ATT_SMEM_FLOATS (128 * 68 * 2 + 64 * 68 + 64 * 128)
#define ATT_SMEM_BYTES  (ATT_SMEM_FLOATS * 4)

__global__ void __launch_bounds__(256) attn_kernel(const float* __restrict__ qkv,
                                                   float* __restrict__ attnOut)
{
    const int qt = blockIdx.x;
    const int h  = blockIdx.y;
    const int b  = blockIdx.z;
    const int kh = h >> 2;                 // jnp.repeat(k, 4, axis=2) => kv = h/4

    extern __shared__ float smem[];
    float* Qt = smem;                      // 128*68
    float* Kt = Qt + 128 * 68;             // 128*68
    float* Pt = Kt + 128 * 68;             // 64*68
    float* Vs = Pt + 64 * 68;              // 64*128

    const int t  = threadIdx.x;
    const int tx = t & 15;
    const int ty = t >> 4;
    const int i0 = ty * 4;

    // load Q tile (d-major, contiguous rows of 64 floats)
    const float* qbase = g_qT + ((size_t)(b * NH + h) * HD) * S_LEN + qt * 64;
#pragma unroll
    for (int u = 0; u < 8; u++) {
        int id = t + u * 256;
        int d = id >> 4, j4 = id & 15;
        *(float4*)(Qt + d * 68 + j4 * 4) =
            *(const float4*)(qbase + (size_t)d * S_LEN + j4 * 4);
    }

    float o[4][8];
#pragma unroll
    for (int i = 0; i < 4; i++)
#pragma unroll
        for (int j = 0; j < 8; j++) o[i][j] = 0.f;
    float m[4] = {-1e30f, -1e30f, -1e30f, -1e30f};
    float l[4] = {0.f, 0.f, 0.f, 0.f};

    const float* kbase = g_kT + ((size_t)(b * NKV + kh) * HD) * S_LEN;
    const float* vbase = qkv + ((size_t)(b * S_LEN)) * QKVN + VOFF + kh * HD;
    const float SC = 0.08838834764831843f;   // 1/sqrt(128)

    for (int kt = 0; kt <= qt; kt++) {
        __syncthreads();   // previous PV done reading Kt/Vs/Pt (also covers Qt on iter 0)
#pragma unroll
        for (int u = 0; u < 8; u++) {
            int id = t + u * 256;
            int d = id >> 4, j4 = id & 15;
            *(float4*)(Kt + d * 68 + j4 * 4) =
                *(const float4*)(kbase + (size_t)d * S_LEN + kt * 64 + j4 * 4);
        }
#pragma unroll
        for (int u = 0; u < 8; u++) {
            int id = t + u * 256;
            int j = id >> 5, d4 = id & 31;
            *(float4*)(Vs + j * 128 + d4 * 4) =
                *(const float4*)(vbase + (size_t)(kt * 64 + j) * QKVN + d4 * 4);
        }
        __syncthreads();

        // ---- scores: s = Q K^T over d ----
        float s4[4][4];
#pragma unroll
        for (int i = 0; i < 4; i++)
#pragma unroll
            for (int j = 0; j < 4; j++) s4[i][j] = 0.f;

#pragma unroll 4
        for (int d = 0; d < 128; d++) {
            float4 aq = *(const float4*)(Qt + d * 68 + i0);
            float4 bk = *(const float4*)(Kt + d * 68 + tx * 4);
            float av[4] = {aq.x, aq.y, aq.z, aq.w};
            float bv[4] = {bk.x, bk.y, bk.z, bk.w};
#pragma unroll
            for (int ii = 0; ii < 4; ii++)
#pragma unroll
                for (int jj = 0; jj < 4; jj++)
                    s4[ii][jj] = fmaf(av[ii], bv[jj], s4[ii][jj]);
        }

        // scale + causal mask (only diagonal tile needs masking)
        if (kt == qt) {
#pragma unroll
            for (int ii = 0; ii < 4; ii++)
#pragma unroll
                for (int jj = 0; jj < 4; jj++)
                    s4[ii][jj] = (tx * 4 + jj > i0 + ii) ? -1e30f : s4[ii][jj] * SC;
        } else {
#pragma unroll
            for (int ii = 0; ii < 4; ii++)
#pragma unroll
                for (int jj = 0; jj < 4; jj++) s4[ii][jj] *= SC;
        }

        // ---- online softmax (row stats shared by the 16 tx-threads via shfl) ----
#pragma unroll
        for (int ii = 0; ii < 4; ii++) {
            float mt = fmaxf(fmaxf(s4[ii][0], s4[ii][1]), fmaxf(s4[ii][2], s4[ii][3]));
#pragma unroll
            for (int off = 8; off > 0; off >>= 1)
                mt = fmaxf(mt, __shfl_xor_sync(0xffffffffu, mt, off));
            float mnew = fmaxf(m[ii], mt);
            float sc = __expf(m[ii] - mnew);
            float rs = 0.f;
#pragma unroll
            for (int jj = 0; jj < 4; jj++) {
                float p = __expf(s4[ii][jj] - mnew);
                s4[ii][jj] = p;
                rs += p;
            }
#pragma unroll
            for (int off = 8; off > 0; off >>= 1)
                rs += __shfl_xor_sync(0xffffffffu, rs, off);
            l[ii] = l[ii] * sc + rs;
            m[ii] = mnew;
#pragma unroll
            for (int dd = 0; dd < 8; dd++) o[ii][dd] *= sc;
        }

        // write probs transposed: Pt[j][i]
#pragma unroll
        for (int jj = 0; jj < 4; jj++)
#pragma unroll
            for (int ii = 0; ii < 4; ii++)
                Pt[(tx * 4 + jj) * 68 + i0 + ii] = s4[ii][jj];
        __syncthreads();

        // ---- PV: O += P V ----
#pragma unroll 2
        for (int j = 0; j < 64; j++) {
            float4 ap = *(const float4*)(Pt + j * 68 + i0);
            float4 b0 = *(const float4*)(Vs + j * 128 + tx * 8);
            float4 b1 = *(const float4*)(Vs + j * 128 + tx * 8 + 4);
            float av[4] = {ap.x, ap.y, ap.z, ap.w};
            float bv[8] = {b0.x, b0.y, b0.z, b0.w, b1.x, b1.y, b1.z, b1.w};
#pragma unroll
            for (int ii = 0; ii < 4; ii++)
#pragma unroll
                for (int dd = 0; dd < 8; dd++)
                    o[ii][dd] = fmaf(av[ii], bv[dd], o[ii][dd]);
        }
    }

    // ---- normalize and write [b][s][h*128+d] (GEMM-ready layout) ----
#pragma unroll
    for (int ii = 0; ii < 4; ii++) {
        float inv = 1.0f / l[ii];
        float* dst = attnOut +
                     (size_t)(b * S_LEN + qt * 64 + i0 + ii) * HID + h * HD + tx * 8;
        float4 r0 = make_float4(o[ii][0] * inv, o[ii][1] * inv, o[ii][2] * inv, o[ii][3] * inv);
        float4 r1 = make_float4(o[ii][4] * inv, o[ii][5] * inv, o[ii][6] * inv, o[ii][7] * inv);
        *(float4*)(dst)     = r0;
        *(float4*)(dst + 4) = r1;
    }
}

// ---------------- launch ------------------------------------------------------
extern "C" void kernel_launch(void* const* d_in, const int* in_sizes, int n_in,
                              void* d_out, int out_size)
{
    const int*   positions = (const int*)  d_in[0];
    const float* hidden    = (const float*)d_in[1];
    const float* w_qkv     = (const float*)d_in[2];
    const float* w_o       = (const float*)d_in[3];
    float*       out       = (float*)d_out;

    // Resolve once (first call is the non-captured correctness run); captured
    // replays then contain only the kernel launches.
    static float* qkv_p = nullptr;
    static float* attn_p = nullptr;
    static bool   init_done = false;
    if (!init_done) {
        cudaGetSymbolAddress((void**)&qkv_p,  g_qkv);
        cudaGetSymbolAddress((void**)&attn_p, g_attn);
        cudaFuncSetAttribute(attn_kernel,
                             cudaFuncAttributeMaxDynamicSharedMemorySize,
                             ATT_SMEM_BYTES);
        init_done = true;
    }

    // 1) inv_freq table (cheap, deterministic every call)
    init_invfreq_kernel<<<1, 64>>>();

    // 2) qkv = hidden @ w_qkv   (M=4096, N=6144, K=4096)
    sgemm_kernel<<<dim3(QKVN / 128, (BATCH * S_LEN) / 128), 256>>>(
        hidden, w_qkv, qkv_p, QKVN, HID);

    // 3) RoPE + transpose Q/K into [b][head][d][s]
    rope_kernel<<<(BATCH * 40 * S_LEN * 64) / 256, 256>>>(qkv_p, positions);

    // 4) causal GQA flash attention
    attn_kernel<<<dim3(S_LEN / 64, NH, BATCH), 256, ATT_SMEM_BYTES>>>(qkv_p, attn_p);

    // 5) out = attn @ w_o       (M=4096, N=4096, K=4096)
    sgemm_kernel<<<dim3(HID / 128, (BATCH * S_LEN) / 128), 256>>>(
        attn_p, w_o, out, HID, HID);
}

// round 8
// speedup vs baseline: 1.6898x; 1.6898x over previous
#include <cuda_runtime.h>
#include <cuda_bf16.h>
#include <cstdint>
#include <math.h>

#define BATCH 2
#define S_LEN 2048
#define HID   4096
#define NH    32
#define NKV   8
#define HD    128
#define QKVN  6144          // Q 4096 | K 1024 | V 1024
#define VOFF  5120          // Q_SIZE + KV_SIZE
#define KDIM  4096          // GEMM K (reduction) for both projections

// ---------------- scratch (no allocation allowed -> device globals) ----------
__device__ float g_qkv [BATCH * S_LEN * QKVN];      // qkv projection output (fp32)
__device__ float g_qT  [BATCH * NH  * HD * S_LEN];  // rope'd Q, layout [b][h][d][s]
__device__ float g_kT  [BATCH * NKV * HD * S_LEN];  // rope'd K, layout [b][kh][d][s]
__device__ float g_attn[BATCH * S_LEN * HID];       // attention output (pre w_o)
__device__ float g_invfreq[64];

// bf16 split operands for the tensor-core GEMMs
__device__ __nv_bfloat16 g_Ahi [4096 * 4096];       // A hi (hidden, then attn)
__device__ __nv_bfloat16 g_Alo [4096 * 4096];       // A lo
__device__ __nv_bfloat16 g_Bqh [QKVN * 4096];       // w_qkv^T hi  [N=6144][K=4096]
__device__ __nv_bfloat16 g_Bql [QKVN * 4096];       // w_qkv^T lo
__device__ __nv_bfloat16 g_Boh [4096 * 4096];       // w_o^T hi    [N=4096][K=4096]
__device__ __nv_bfloat16 g_Bol [4096 * 4096];       // w_o^T lo

// ================= helpers ====================================================
__device__ __forceinline__ uint32_t smem_u32(const void* p) {
    uint32_t a;
    asm("{ .reg .u64 t; cvta.to.shared.u64 t, %1; cvt.u32.u64 %0, t; }" : "=r"(a) : "l"(p));
    return a;
}

#define LDSM_X4(r, addr) \
    asm volatile("ldmatrix.sync.aligned.m8n8.x4.shared.b16 {%0,%1,%2,%3}, [%4];" \
        : "=r"((r)[0]), "=r"((r)[1]), "=r"((r)[2]), "=r"((r)[3]) : "r"(addr))

#define MMA16816(c, a, b0, b1) \
    asm volatile("mma.sync.aligned.m16n8k16.row.col.f32.bf16.bf16.f32 " \
        "{%0,%1,%2,%3}, {%4,%5,%6,%7}, {%8,%9}, {%0,%1,%2,%3};" \
        : "+f"((c)[0]), "+f"((c)[1]), "+f"((c)[2]), "+f"((c)[3]) \
        : "r"((a)[0]), "r"((a)[1]), "r"((a)[2]), "r"((a)[3]), "r"(b0), "r"(b1))

#define CP_ASYNC16(dst, src) \
    asm volatile("cp.async.cg.shared.global [%0], [%1], 16;" :: "r"(dst), "l"(src))
#define CP_COMMIT() asm volatile("cp.async.commit_group;" ::: "memory")
#define CP_WAIT(n)  asm volatile("cp.async.wait_group %0;" :: "n"(n) : "memory")

extern __shared__ char dynsmem[];

// ---------------- inv_freq table ---------------------------------------------
__global__ void init_invfreq_kernel() {
    int i = threadIdx.x;
    if (i < 64) {
        const float LOG2_10000 = 13.28771237954945f;
        g_invfreq[i] = exp2f(-((float)(2 * i) / 128.0f) * LOG2_10000);
    }
}

// ---------------- fp32 -> bf16 hi/lo split (elementwise, float4) --------------
__global__ void __launch_bounds__(256) split_a_kernel(
    const float* __restrict__ X, __nv_bfloat16* __restrict__ hi,
    __nv_bfloat16* __restrict__ lo, int n4)
{
    int i = blockIdx.x * 256 + threadIdx.x;
    if (i >= n4) return;
    float4 v = ((const float4*)X)[i];
    __nv_bfloat16 h0 = __float2bfloat16(v.x), h1 = __float2bfloat16(v.y);
    __nv_bfloat16 h2 = __float2bfloat16(v.z), h3 = __float2bfloat16(v.w);
    __nv_bfloat16 l0 = __float2bfloat16(v.x - __bfloat162float(h0));
    __nv_bfloat16 l1 = __float2bfloat16(v.y - __bfloat162float(h1));
    __nv_bfloat16 l2 = __float2bfloat16(v.z - __bfloat162float(h2));
    __nv_bfloat16 l3 = __float2bfloat16(v.w - __bfloat162float(h3));
    ((__nv_bfloat162*)hi)[i * 2]     = __halves2bfloat162(h0, h1);
    ((__nv_bfloat162*)hi)[i * 2 + 1] = __halves2bfloat162(h2, h3);
    ((__nv_bfloat162*)lo)[i * 2]     = __halves2bfloat162(l0, l1);
    ((__nv_bfloat162*)lo)[i * 2 + 1] = __halves2bfloat162(l2, l3);
}

// ---------------- W[K,N] fp32 -> Bt[N,K] bf16 hi/lo (tiled transpose) ---------
__global__ void __launch_bounds__(256) transpose_split_kernel(
    const float* __restrict__ W, __nv_bfloat16* __restrict__ bhi,
    __nv_bfloat16* __restrict__ blo, int K, int N)
{
    __shared__ float tile[32][33];
    int tx = threadIdx.x & 31, ty = threadIdx.x >> 5;   // 32 x 8
    int k0 = blockIdx.y * 32, n0 = blockIdx.x * 32;
#pragma unroll
    for (int r = 0; r < 4; r++)
        tile[ty + r * 8][tx] = W[(size_t)(k0 + ty + r * 8) * N + n0 + tx];
    __syncthreads();
#pragma unroll
    for (int r = 0; r < 4; r++) {
        int n = n0 + ty + r * 8;
        int k = k0 + tx;
        float x = tile[tx][ty + r * 8];
        __nv_bfloat16 h = __float2bfloat16(x);
        __nv_bfloat16 l = __float2bfloat16(x - __bfloat162float(h));
        bhi[(size_t)n * K + k] = h;
        blo[(size_t)n * K + k] = l;
    }
}

// ---------------- mma.sync split-bf16 GEMM ------------------------------------
// C[M x Ntot] = A[M x 4096] @ W[4096 x Ntot]; A row-major hi/lo bf16,
// B pre-transposed [Ntot x 4096] hi/lo bf16.
// Block tile 128x128, BK=32, 256 threads (8 warps as 2x4, warp tile 64x32).
// smem per stage: 4 tiles (Ahi,Alo,Bhi,Blo) of 128 rows x 80B pitch = 40960 B.
#define GPITCH 80
#define GTSZ   (128 * GPITCH)          // 10240
#define GSTG   (4 * GTSZ)              // 40960
#define GEMM_SMEM_BYTES (2 * GSTG)     // 81920

__global__ void __launch_bounds__(256, 1) gemm_mma_kernel(
    const __nv_bfloat16* __restrict__ Ahi, const __nv_bfloat16* __restrict__ Alo,
    const __nv_bfloat16* __restrict__ Bhi, const __nv_bfloat16* __restrict__ Blo,
    float* __restrict__ C, int Ntot)
{
    const uint32_t sb = smem_u32(dynsmem);
    const int t = threadIdx.x;
    const int wid = t >> 5, lane = t & 31;
    const int bm = blockIdx.y, bn = blockIdx.x;
    const int wm = (wid >> 2) * 64;        // 0 or 64
    const int wn = (wid & 3) * 32;         // 0..96

    const __nv_bfloat16* gsrc[4] = {
        Ahi + (size_t)(bm * 128) * KDIM,
        Alo + (size_t)(bm * 128) * KDIM,
        Bhi + (size_t)(bn * 128) * KDIM,
        Blo + (size_t)(bn * 128) * KDIM };

    // loader: each tensor = 128 rows x 64B; 256 threads -> row = t>>1, 32B each
    const int lrow = t >> 1;
    const int lq   = (t & 1) * 2;          // 16B-unit index 0 or 2

    auto load_chunk = [&](int c, int s) {
        uint32_t base = sb + s * GSTG + lrow * GPITCH + lq * 16;
#pragma unroll
        for (int tens = 0; tens < 4; tens++) {
            const __nv_bfloat16* src = gsrc[tens] + (size_t)lrow * KDIM + c * 32 + lq * 8;
            uint32_t d = base + tens * GTSZ;
            CP_ASYNC16(d, src);
            CP_ASYNC16(d + 16, src + 8);
        }
    };

    float acc[4][4][4];
#pragma unroll
    for (int a = 0; a < 4; a++)
#pragma unroll
        for (int b = 0; b < 4; b++)
#pragma unroll
            for (int c = 0; c < 4; c++) acc[a][b][c] = 0.f;

    const int NCH = KDIM / 32;     // 128 chunks

    load_chunk(0, 0);
    CP_COMMIT();

    for (int i = 0; i < NCH; i++) {
        const int s = i & 1;
        if (i + 1 < NCH) {
            load_chunk(i + 1, (i + 1) & 1);
            CP_COMMIT();
            CP_WAIT(1);
        } else {
            CP_WAIT(0);
        }
        __syncthreads();   // chunk i visible to all; prior compute done (tail barrier)

        const uint32_t sA = sb + s * GSTG;
        const uint32_t sB = sA + 2 * GTSZ;

#pragma unroll
        for (int ks = 0; ks < 2; ks++) {
            const int k0b = ks * 32;   // byte offset of 16-elem k group
            uint32_t a_hi[4][4], a_lo[4][4], b_hi[2][4], b_lo[2][4];
#pragma unroll
            for (int mt = 0; mt < 4; mt++) {
                uint32_t ad = sA + (uint32_t)(wm + mt * 16 + (lane & 15)) * GPITCH
                            + k0b + ((lane >> 4) << 4);
                LDSM_X4(a_hi[mt], ad);
                LDSM_X4(a_lo[mt], ad + GTSZ);
            }
#pragma unroll
            for (int p = 0; p < 2; p++) {
                uint32_t bd = sB + (uint32_t)(wn + p * 16 + ((lane >> 4) << 3) + (lane & 7)) * GPITCH
                            + k0b + (((lane >> 3) & 1) << 4);
                LDSM_X4(b_hi[p], bd);
                LDSM_X4(b_lo[p], bd + GTSZ);
            }
#pragma unroll
            for (int mt = 0; mt < 4; mt++)
#pragma unroll
                for (int nt = 0; nt < 4; nt++) {
                    const int p = nt >> 1, hh = (nt & 1) * 2;
                    MMA16816(acc[mt][nt], a_hi[mt], b_hi[p][hh], b_hi[p][hh + 1]);
                    MMA16816(acc[mt][nt], a_hi[mt], b_lo[p][hh], b_lo[p][hh + 1]);
                    MMA16816(acc[mt][nt], a_lo[mt], b_hi[p][hh], b_hi[p][hh + 1]);
                }
        }
        __syncthreads();   // all warps done with stage s before it is reloaded
    }

    // ---- epilogue: fragments -> C (row t/4, col 2*(t%4); rows +8 for c2,c3) ----
#pragma unroll
    for (int mt = 0; mt < 4; mt++)
#pragma unroll
        for (int nt = 0; nt < 4; nt++) {
            int row = bm * 128 + wm + mt * 16 + (lane >> 2);
            int col = bn * 128 + wn + nt * 8 + (lane & 3) * 2;
            float2 v0 = make_float2(acc[mt][nt][0], acc[mt][nt][1]);
            float2 v1 = make_float2(acc[mt][nt][2], acc[mt][nt][3]);
            *(float2*)(C + (size_t)row * Ntot + col)       = v0;
            *(float2*)(C + (size_t)(row + 8) * Ntot + col) = v1;
        }
}

// ---------------- RoPE (NeoX) + transpose into [b][head][d][s] ----------------
__global__ void rope_kernel(const float* __restrict__ qkv,
                            const int*   __restrict__ positions)
{
    int idx = blockIdx.x * 256 + threadIdx.x;
    int i  = idx & 63;
    int s  = (idx >> 6) & (S_LEN - 1);
    int r  = idx >> 17;
    int hh = r % 40;
    int b  = r / 40;

    float pos = (float)positions[b * S_LEN + s];
    float ang = pos * g_invfreq[i];
    float sn, cs;
    sincosf(ang, &sn, &cs);

    if (hh < 32) {
        const float* src = qkv + ((size_t)(b * S_LEN + s)) * QKVN + hh * HD;
        float x1 = src[i], x2 = src[i + 64];
        float* dst = g_qT + ((size_t)(b * NH + hh) * HD) * S_LEN;
        dst[(size_t)i * S_LEN + s]        = x1 * cs - x2 * sn;
        dst[(size_t)(i + 64) * S_LEN + s] = x2 * cs + x1 * sn;
    } else {
        int kh = hh - 32;
        const float* src = qkv + ((size_t)(b * S_LEN + s)) * QKVN + HID + kh * HD;
        float x1 = src[i], x2 = src[i + 64];
        float* dst = g_kT + ((size_t)(b * NKV + kh) * HD) * S_LEN;
        dst[(size_t)i * S_LEN + s]        = x1 * cs - x2 * sn;
        dst[(size_t)(i + 64) * S_LEN + s] = x2 * cs + x1 * sn;
    }
}

// ---------------- Flash attention, causal, GQA (rep=4) ------------------------
#define ATT_SMEM_FLOATS (128 * 68 * 2 + 64 * 68 + 64 * 128)
#define ATT_SMEM_BYTES  (ATT_SMEM_FLOATS * 4)

__global__ void __launch_bounds__(256) attn_kernel(const float* __restrict__ qkv,
                                                   float* __restrict__ attnOut)
{
    const int qt = blockIdx.x;
    const int h  = blockIdx.y;
    const int b  = blockIdx.z;
    const int kh = h >> 2;

    float* smemf = (float*)dynsmem;
    float* Qt = smemf;
    float* Kt = Qt + 128 * 68;
    float* Pt = Kt + 128 * 68;
    float* Vs = Pt + 64 * 68;

    const int t  = threadIdx.x;
    const int tx = t & 15;
    const int ty = t >> 4;
    const int i0 = ty * 4;

    const float* qbase = g_qT + ((size_t)(b * NH + h) * HD) * S_LEN + qt * 64;
#pragma unroll
    for (int u = 0; u < 8; u++) {
        int id = t + u * 256;
        int d = id >> 4, j4 = id & 15;
        *(float4*)(Qt + d * 68 + j4 * 4) =
            *(const float4*)(qbase + (size_t)d * S_LEN + j4 * 4);
    }

    float o[4][8];
#pragma unroll
    for (int i = 0; i < 4; i++)
#pragma unroll
        for (int j = 0; j < 8; j++) o[i][j] = 0.f;
    float m[4] = {-1e30f, -1e30f, -1e30f, -1e30f};
    float l[4] = {0.f, 0.f, 0.f, 0.f};

    const float* kbase = g_kT + ((size_t)(b * NKV + kh) * HD) * S_LEN;
    const float* vbase = qkv + ((size_t)(b * S_LEN)) * QKVN + VOFF + kh * HD;
    const float SC = 0.08838834764831843f;

    for (int kt = 0; kt <= qt; kt++) {
        __syncthreads();
#pragma unroll
        for (int u = 0; u < 8; u++) {
            int id = t + u * 256;
            int d = id >> 4, j4 = id & 15;
            *(float4*)(Kt + d * 68 + j4 * 4) =
                *(const float4*)(kbase + (size_t)d * S_LEN + kt * 64 + j4 * 4);
        }
#pragma unroll
        for (int u = 0; u < 8; u++) {
            int id = t + u * 256;
            int j = id >> 5, d4 = id & 31;
            *(float4*)(Vs + j * 128 + d4 * 4) =
                *(const float4*)(vbase + (size_t)(kt * 64 + j) * QKVN + d4 * 4);
        }
        __syncthreads();

        float s4[4][4];
#pragma unroll
        for (int i = 0; i < 4; i++)
#pragma unroll
            for (int j = 0; j < 4; j++) s4[i][j] = 0.f;

#pragma unroll 4
        for (int d = 0; d < 128; d++) {
            float4 aq = *(const float4*)(Qt + d * 68 + i0);
            float4 bk = *(const float4*)(Kt + d * 68 + tx * 4);
            float av[4] = {aq.x, aq.y, aq.z, aq.w};
            float bv[4] = {bk.x, bk.y, bk.z, bk.w};
#pragma unroll
            for (int ii = 0; ii < 4; ii++)
#pragma unroll
                for (int jj = 0; jj < 4; jj++)
                    s4[ii][jj] = fmaf(av[ii], bv[jj], s4[ii][jj]);
        }

        if (kt == qt) {
#pragma unroll
            for (int ii = 0; ii < 4; ii++)
#pragma unroll
                for (int jj = 0; jj < 4; jj++)
                    s4[ii][jj] = (tx * 4 + jj > i0 + ii) ? -1e30f : s4[ii][jj] * SC;
        } else {
#pragma unroll
            for (int ii = 0; ii < 4; ii++)
#pragma unroll
                for (int jj = 0; jj < 4; jj++) s4[ii][jj] *= SC;
        }

#pragma unroll
        for (int ii = 0; ii < 4; ii++) {
            float mt = fmaxf(fmaxf(s4[ii][0], s4[ii][1]), fmaxf(s4[ii][2], s4[ii][3]));
#pragma unroll
            for (int off = 8; off > 0; off >>= 1)
                mt = fmaxf(mt, __shfl_xor_sync(0xffffffffu, mt, off));
            float mnew = fmaxf(m[ii], mt);
            float sc = __expf(m[ii] - mnew);
            float rs = 0.f;
#pragma unroll
            for (int jj = 0; jj < 4; jj++) {
                float p = __expf(s4[ii][jj] - mnew);
                s4[ii][jj] = p;
                rs += p;
            }
#pragma unroll
            for (int off = 8; off > 0; off >>= 1)
                rs += __shfl_xor_sync(0xffffffffu, rs, off);
            l[ii] = l[ii] * sc + rs;
            m[ii] = mnew;
#pragma unroll
            for (int dd = 0; dd < 8; dd++) o[ii][dd] *= sc;
        }

#pragma unroll
        for (int jj = 0; jj < 4; jj++)
#pragma unroll
            for (int ii = 0; ii < 4; ii++)
                Pt[(tx * 4 + jj) * 68 + i0 + ii] = s4[ii][jj];
        __syncthreads();

#pragma unroll 2
        for (int j = 0; j < 64; j++) {
            float4 ap = *(const float4*)(Pt + j * 68 + i0);
            float4 b0 = *(const float4*)(Vs + j * 128 + tx * 8);
            float4 b1 = *(const float4*)(Vs + j * 128 + tx * 8 + 4);
            float av[4] = {ap.x, ap.y, ap.z, ap.w};
            float bv[8] = {b0.x, b0.y, b0.z, b0.w, b1.x, b1.y, b1.z, b1.w};
#pragma unroll
            for (int ii = 0; ii < 4; ii++)
#pragma unroll
                for (int dd = 0; dd < 8; dd++)
                    o[ii][dd] = fmaf(av[ii], bv[dd], o[ii][dd]);
        }
    }

#pragma unroll
    for (int ii = 0; ii < 4; ii++) {
        float inv = 1.0f / l[ii];
        float* dst = attnOut +
                     (size_t)(b * S_LEN + qt * 64 + i0 + ii) * HID + h * HD + tx * 8;
        float4 r0 = make_float4(o[ii][0] * inv, o[ii][1] * inv, o[ii][2] * inv, o[ii][3] * inv);
        float4 r1 = make_float4(o[ii][4] * inv, o[ii][5] * inv, o[ii][6] * inv, o[ii][7] * inv);
        *(float4*)(dst)     = r0;
        *(float4*)(dst + 4) = r1;
    }
}

// ---------------- launch ------------------------------------------------------
extern "C" void kernel_launch(void* const* d_in, const int* in_sizes, int n_in,
                              void* d_out, int out_size)
{
    const int*   positions = (const int*)  d_in[0];
    const float* hidden    = (const float*)d_in[1];
    const float* w_qkv     = (const float*)d_in[2];
    const float* w_o       = (const float*)d_in[3];
    float*       out       = (float*)d_out;

    static float *qkv_p, *attn_p;
    static __nv_bfloat16 *ahi, *alo, *bqh, *bql, *boh, *bol;
    static bool init_done = false;
    if (!init_done) {
        cudaGetSymbolAddress((void**)&qkv_p,  g_qkv);
        cudaGetSymbolAddress((void**)&attn_p, g_attn);
        cudaGetSymbolAddress((void**)&ahi, g_Ahi);
        cudaGetSymbolAddress((void**)&alo, g_Alo);
        cudaGetSymbolAddress((void**)&bqh, g_Bqh);
        cudaGetSymbolAddress((void**)&bql, g_Bql);
        cudaGetSymbolAddress((void**)&boh, g_Boh);
        cudaGetSymbolAddress((void**)&bol, g_Bol);
        cudaFuncSetAttribute(attn_kernel,
                             cudaFuncAttributeMaxDynamicSharedMemorySize, ATT_SMEM_BYTES);
        cudaFuncSetAttribute(gemm_mma_kernel,
                             cudaFuncAttributeMaxDynamicSharedMemorySize, GEMM_SMEM_BYTES);
        init_done = true;
    }

    const int M = BATCH * S_LEN;   // 4096

    init_invfreq_kernel<<<1, 64>>>();

    // split inputs / transpose+split weights
    split_a_kernel<<<(M * KDIM / 4 + 255) / 256, 256>>>(hidden, ahi, alo, M * KDIM / 4);
    transpose_split_kernel<<<dim3(QKVN / 32, KDIM / 32), 256>>>(w_qkv, bqh, bql, KDIM, QKVN);
    transpose_split_kernel<<<dim3(HID / 32, KDIM / 32), 256>>>(w_o, boh, bol, KDIM, HID);

    // qkv = hidden @ w_qkv  (tensor cores via mma.sync)
    gemm_mma_kernel<<<dim3(QKVN / 128, M / 128), 256, GEMM_SMEM_BYTES>>>(
        ahi, alo, bqh, bql, qkv_p, QKVN);

    rope_kernel<<<(BATCH * 40 * S_LEN * 64) / 256, 256>>>(qkv_p, positions);

    attn_kernel<<<dim3(S_LEN / 64, NH, BATCH), 256, ATT_SMEM_BYTES>>>(qkv_p, attn_p);

    // out = attn @ w_o  (tensor cores via mma.sync)
    split_a_kernel<<<(M * HID / 4 + 255) / 256, 256>>>(attn_p, ahi, alo, M * HID / 4);
    gemm_mma_kernel<<<dim3(HID / 128, M / 128), 256, GEMM_SMEM_BYTES>>>(
        ahi, alo, boh, bol, out, HID);
}

// round 9
// speedup vs baseline: 2.4124x; 1.4276x over previous
#include <cuda_runtime.h>
#include <cuda_bf16.h>
#include <cstdint>
#include <math.h>

#define BATCH 2
#define S_LEN 2048
#define HID   4096
#define NH    32
#define NKV   8
#define HD    128
#define QKVN  6144          // Q 4096 | K 1024 | V 1024
#define VOFF  5120          // Q_SIZE + KV_SIZE
#define KDIM  4096          // GEMM K (reduction) for both projections

// ---------------- scratch (no allocation allowed -> device globals) ----------
__device__ float g_qkv [BATCH * S_LEN * QKVN];      // qkv projection output (fp32)
__device__ float g_invfreq[64];

// bf16 split operands for the tensor-core GEMMs
__device__ __nv_bfloat16 g_Ahi [4096 * 4096];       // A hi (hidden; then attn out)
__device__ __nv_bfloat16 g_Alo [4096 * 4096];       // A lo
__device__ __nv_bfloat16 g_Bqh [QKVN * 4096];       // w_qkv^T hi  [N=6144][K=4096]
__device__ __nv_bfloat16 g_Bql [QKVN * 4096];       // w_qkv^T lo
__device__ __nv_bfloat16 g_Boh [4096 * 4096];       // w_o^T hi    [N=4096][K=4096]
__device__ __nv_bfloat16 g_Bol [4096 * 4096];       // w_o^T lo

// bf16 split attention operands
__device__ __nv_bfloat16 g_Qh [BATCH * NH  * S_LEN * HD];  // [b][h][s][d]
__device__ __nv_bfloat16 g_Ql [BATCH * NH  * S_LEN * HD];
__device__ __nv_bfloat16 g_Kh [BATCH * NKV * S_LEN * HD];  // [b][kh][s][d]
__device__ __nv_bfloat16 g_Kl [BATCH * NKV * S_LEN * HD];
__device__ __nv_bfloat16 g_Vh [BATCH * NKV * HD * S_LEN];  // [b][kh][d][s]
__device__ __nv_bfloat16 g_Vl [BATCH * NKV * HD * S_LEN];

// ================= helpers ====================================================
__device__ __forceinline__ uint32_t smem_u32(const void* p) {
    uint32_t a;
    asm("{ .reg .u64 t; cvta.to.shared.u64 t, %1; cvt.u32.u64 %0, t; }" : "=r"(a) : "l"(p));
    return a;
}

#define LDSM_X4(r, addr) \
    asm volatile("ldmatrix.sync.aligned.m8n8.x4.shared.b16 {%0,%1,%2,%3}, [%4];" \
        : "=r"((r)[0]), "=r"((r)[1]), "=r"((r)[2]), "=r"((r)[3]) : "r"(addr))

#define MMA16816(c, a, b0, b1) \
    asm volatile("mma.sync.aligned.m16n8k16.row.col.f32.bf16.bf16.f32 " \
        "{%0,%1,%2,%3}, {%4,%5,%6,%7}, {%8,%9}, {%0,%1,%2,%3};" \
        : "+f"((c)[0]), "+f"((c)[1]), "+f"((c)[2]), "+f"((c)[3]) \
        : "r"((a)[0]), "r"((a)[1]), "r"((a)[2]), "r"((a)[3]), "r"(b0), "r"(b1))

#define CP_ASYNC16(dst, src) \
    asm volatile("cp.async.cg.shared.global [%0], [%1], 16;" :: "r"(dst), "l"(src))
#define CP_COMMIT() asm volatile("cp.async.commit_group;" ::: "memory")
#define CP_WAIT(n)  asm volatile("cp.async.wait_group %0;" :: "n"(n) : "memory")

__device__ __forceinline__ void split2(float a, float b, uint32_t& hi, uint32_t& lo) {
    __nv_bfloat16 ha = __float2bfloat16(a), hb = __float2bfloat16(b);
    __nv_bfloat16 la = __float2bfloat16(a - __bfloat162float(ha));
    __nv_bfloat16 lb = __float2bfloat16(b - __bfloat162float(hb));
    __nv_bfloat162 H = __halves2bfloat162(ha, hb);
    __nv_bfloat162 L = __halves2bfloat162(la, lb);
    hi = *(uint32_t*)&H;  lo = *(uint32_t*)&L;
}

extern __shared__ char dynsmem[];

// ---------------- inv_freq table ---------------------------------------------
__global__ void init_invfreq_kernel() {
    int i = threadIdx.x;
    if (i < 64) {
        const float LOG2_10000 = 13.28771237954945f;
        g_invfreq[i] = exp2f(-((float)(2 * i) / 128.0f) * LOG2_10000);
    }
}

// ---------------- fp32 -> bf16 hi/lo split (elementwise, float4) --------------
__global__ void __launch_bounds__(256) split_a_kernel(
    const float* __restrict__ X, __nv_bfloat16* __restrict__ hi,
    __nv_bfloat16* __restrict__ lo, int n4)
{
    int i = blockIdx.x * 256 + threadIdx.x;
    if (i >= n4) return;
    float4 v = ((const float4*)X)[i];
    uint32_t h0, l0, h1, l1;
    split2(v.x, v.y, h0, l0);
    split2(v.z, v.w, h1, l1);
    ((uint32_t*)hi)[i * 2]     = h0;
    ((uint32_t*)hi)[i * 2 + 1] = h1;
    ((uint32_t*)lo)[i * 2]     = l0;
    ((uint32_t*)lo)[i * 2 + 1] = l1;
}

// ---------------- W[K,N] fp32 -> Bt[N,K] bf16 hi/lo (tiled transpose) ---------
__global__ void __launch_bounds__(256) transpose_split_kernel(
    const float* __restrict__ W, __nv_bfloat16* __restrict__ bhi,
    __nv_bfloat16* __restrict__ blo, int K, int N)
{
    __shared__ float tile[32][33];
    int tx = threadIdx.x & 31, ty = threadIdx.x >> 5;   // 32 x 8
    int k0 = blockIdx.y * 32, n0 = blockIdx.x * 32;
#pragma unroll
    for (int r = 0; r < 4; r++)
        tile[ty + r * 8][tx] = W[(size_t)(k0 + ty + r * 8) * N + n0 + tx];
    __syncthreads();
#pragma unroll
    for (int r = 0; r < 4; r++) {
        int n = n0 + ty + r * 8;
        int k = k0 + tx;
        float x = tile[tx][ty + r * 8];
        __nv_bfloat16 h = __float2bfloat16(x);
        __nv_bfloat16 l = __float2bfloat16(x - __bfloat162float(h));
        bhi[(size_t)n * K + k] = h;
        blo[(size_t)n * K + k] = l;
    }
}

// ---------------- mma.sync split-bf16 GEMM (unchanged from R8, passed) --------
#define GPITCH 80
#define GTSZ   (128 * GPITCH)
#define GSTG   (4 * GTSZ)
#define GEMM_SMEM_BYTES (2 * GSTG)     // 81920

__global__ void __launch_bounds__(256, 1) gemm_mma_kernel(
    const __nv_bfloat16* __restrict__ Ahi, const __nv_bfloat16* __restrict__ Alo,
    const __nv_bfloat16* __restrict__ Bhi, const __nv_bfloat16* __restrict__ Blo,
    float* __restrict__ C, int Ntot)
{
    const uint32_t sb = smem_u32(dynsmem);
    const int t = threadIdx.x;
    const int wid = t >> 5, lane = t & 31;
    const int bm = blockIdx.y, bn = blockIdx.x;
    const int wm = (wid >> 2) * 64;
    const int wn = (wid & 3) * 32;

    const __nv_bfloat16* gsrc[4] = {
        Ahi + (size_t)(bm * 128) * KDIM,
        Alo + (size_t)(bm * 128) * KDIM,
        Bhi + (size_t)(bn * 128) * KDIM,
        Blo + (size_t)(bn * 128) * KDIM };

    const int lrow = t >> 1;
    const int lq   = (t & 1) * 2;

    auto load_chunk = [&](int c, int s) {
        uint32_t base = sb + s * GSTG + lrow * GPITCH + lq * 16;
#pragma unroll
        for (int tens = 0; tens < 4; tens++) {
            const __nv_bfloat16* src = gsrc[tens] + (size_t)lrow * KDIM + c * 32 + lq * 8;
            uint32_t d = base + tens * GTSZ;
            CP_ASYNC16(d, src);
            CP_ASYNC16(d + 16, src + 8);
        }
    };

    float acc[4][4][4];
#pragma unroll
    for (int a = 0; a < 4; a++)
#pragma unroll
        for (int b = 0; b < 4; b++)
#pragma unroll
            for (int c = 0; c < 4; c++) acc[a][b][c] = 0.f;

    const int NCH = KDIM / 32;

    load_chunk(0, 0);
    CP_COMMIT();

    for (int i = 0; i < NCH; i++) {
        const int s = i & 1;
        if (i + 1 < NCH) {
            load_chunk(i + 1, (i + 1) & 1);
            CP_COMMIT();
            CP_WAIT(1);
        } else {
            CP_WAIT(0);
        }
        __syncthreads();

        const uint32_t sA = sb + s * GSTG;
        const uint32_t sB = sA + 2 * GTSZ;

#pragma unroll
        for (int ks = 0; ks < 2; ks++) {
            const int k0b = ks * 32;
            uint32_t a_hi[4][4], a_lo[4][4], b_hi[2][4], b_lo[2][4];
#pragma unroll
            for (int mt = 0; mt < 4; mt++) {
                uint32_t ad = sA + (uint32_t)(wm + mt * 16 + (lane & 15)) * GPITCH
                            + k0b + ((lane >> 4) << 4);
                LDSM_X4(a_hi[mt], ad);
                LDSM_X4(a_lo[mt], ad + GTSZ);
            }
#pragma unroll
            for (int p = 0; p < 2; p++) {
                uint32_t bd = sB + (uint32_t)(wn + p * 16 + ((lane >> 4) << 3) + (lane & 7)) * GPITCH
                            + k0b + (((lane >> 3) & 1) << 4);
                LDSM_X4(b_hi[p], bd);
                LDSM_X4(b_lo[p], bd + GTSZ);
            }
#pragma unroll
            for (int mt = 0; mt < 4; mt++)
#pragma unroll
                for (int nt = 0; nt < 4; nt++) {
                    const int p = nt >> 1, hh = (nt & 1) * 2;
                    MMA16816(acc[mt][nt], a_hi[mt], b_hi[p][hh], b_hi[p][hh + 1]);
                    MMA16816(acc[mt][nt], a_hi[mt], b_lo[p][hh], b_lo[p][hh + 1]);
                    MMA16816(acc[mt][nt], a_lo[mt], b_hi[p][hh], b_hi[p][hh + 1]);
                }
        }
        __syncthreads();
    }

#pragma unroll
    for (int mt = 0; mt < 4; mt++)
#pragma unroll
        for (int nt = 0; nt < 4; nt++) {
            int row = bm * 128 + wm + mt * 16 + (lane >> 2);
            int col = bn * 128 + wn + nt * 8 + (lane & 3) * 2;
            float2 v0 = make_float2(acc[mt][nt][0], acc[mt][nt][1]);
            float2 v1 = make_float2(acc[mt][nt][2], acc[mt][nt][3]);
            *(float2*)(C + (size_t)row * Ntot + col)       = v0;
            *(float2*)(C + (size_t)(row + 8) * Ntot + col) = v1;
        }
}

// ---------------- RoPE (NeoX) + bf16 hi/lo split, natural [.,s,d] layout ------
__global__ void rope_split_kernel(const float* __restrict__ qkv,
                                  const int*   __restrict__ positions)
{
    int idx = blockIdx.x * 256 + threadIdx.x;
    int i  = idx & 63;
    int s  = (idx >> 6) & (S_LEN - 1);
    int r  = idx >> 17;          // b*40 + hh
    int hh = r % 40;
    int b  = r / 40;

    float pos = (float)positions[b * S_LEN + s];
    float ang = pos * g_invfreq[i];
    float sn, cs;
    sincosf(ang, &sn, &cs);

    if (hh < 32) {
        const float* src = qkv + ((size_t)(b * S_LEN + s)) * QKVN + hh * HD;
        float x1 = src[i], x2 = src[i + 64];
        float y1 = x1 * cs - x2 * sn;
        float y2 = x2 * cs + x1 * sn;
        size_t base = ((size_t)(b * NH + hh) * S_LEN + s) * HD;
        __nv_bfloat16 h1 = __float2bfloat16(y1);
        __nv_bfloat16 h2 = __float2bfloat16(y2);
        g_Qh[base + i]      = h1;
        g_Qh[base + i + 64] = h2;
        g_Ql[base + i]      = __float2bfloat16(y1 - __bfloat162float(h1));
        g_Ql[base + i + 64] = __float2bfloat16(y2 - __bfloat162float(h2));
    } else {
        int kh = hh - 32;
        const float* src = qkv + ((size_t)(b * S_LEN + s)) * QKVN + HID + kh * HD;
        float x1 = src[i], x2 = src[i + 64];
        float y1 = x1 * cs - x2 * sn;
        float y2 = x2 * cs + x1 * sn;
        size_t base = ((size_t)(b * NKV + kh) * S_LEN + s) * HD;
        __nv_bfloat16 h1 = __float2bfloat16(y1);
        __nv_bfloat16 h2 = __float2bfloat16(y2);
        g_Kh[base + i]      = h1;
        g_Kh[base + i + 64] = h2;
        g_Kl[base + i]      = __float2bfloat16(y1 - __bfloat162float(h1));
        g_Kl[base + i + 64] = __float2bfloat16(y2 - __bfloat162float(h2));
    }
}

// ---------------- V: [s][d] fp32 -> [d][s] bf16 hi/lo (tiled transpose) -------
__global__ void __launch_bounds__(256) v_split_kernel(const float* __restrict__ qkv)
{
    __shared__ float tile[32][33];
    int tx = threadIdx.x & 31, ty = threadIdx.x >> 5;   // 32 x 8
    int s0 = blockIdx.x * 32, d0 = blockIdx.y * 32;
    int slab = blockIdx.z;                               // b*NKV + kh
    int b = slab / NKV, kh = slab % NKV;

    const float* src = qkv + (size_t)(b * S_LEN) * QKVN + VOFF + kh * HD;
#pragma unroll
    for (int r = 0; r < 4; r++)
        tile[ty + r * 8][tx] = src[(size_t)(s0 + ty + r * 8) * QKVN + d0 + tx];
    __syncthreads();
#pragma unroll
    for (int r = 0; r < 4; r++) {
        int d = d0 + ty + r * 8;
        int s = s0 + tx;
        float x = tile[tx][ty + r * 8];
        __nv_bfloat16 h = __float2bfloat16(x);
        __nv_bfloat16 l = __float2bfloat16(x - __bfloat162float(h));
        size_t o = ((size_t)(b * NKV + kh) * HD + d) * S_LEN + s;
        g_Vh[o] = h;
        g_Vl[o] = l;
    }
}

// ---------------- mma.sync split-bf16 flash attention -------------------------
// Block = (128 Q rows, head, batch); 256 threads = 8 warps, warp = 16 Q rows.
// K tiles of 64. QK^T: A=Q [s][d], B=K [s][d] (row.col). PV: A=P (frag reuse),
// B=V^T [d][s]. 3-product split-bf16, fp32 accum, online softmax on fragments.
#define AQ_PITCH 272     // 256B row + 16B pad
#define AK_PITCH 272
#define AV_PITCH 144     // 128B row + 16B pad
#define SQ_BYTES (128 * AQ_PITCH)   // 34816
#define SK_BYTES (64  * AK_PITCH)   // 17408
#define SV_BYTES (128 * AV_PITCH)   // 18432
#define ATT_SMEM_BYTES (2 * SQ_BYTES + 2 * SK_BYTES + 2 * SV_BYTES)  // 141312

__global__ void __launch_bounds__(256, 1) attn_mma_kernel(
    __nv_bfloat16* __restrict__ Ohi, __nv_bfloat16* __restrict__ Olo)
{
    const int qt = blockIdx.x;      // 0..15 (128-row tiles)
    const int h  = blockIdx.y;
    const int b  = blockIdx.z;
    const int kh = h >> 2;

    const uint32_t sb  = smem_u32(dynsmem);
    const uint32_t sQh = sb;
    const uint32_t sQl = sQh + SQ_BYTES;
    const uint32_t sKh = sQl + SQ_BYTES;
    const uint32_t sKl = sKh + SK_BYTES;
    const uint32_t sVh = sKl + SK_BYTES;
    const uint32_t sVl = sVh + SV_BYTES;

    const int t = threadIdx.x;
    const int wid = t >> 5, lane = t & 31;
    const int wm = wid * 16;

    // ---- load Q tile (once) ----
    {
        const __nv_bfloat16* q0 = g_Qh + ((size_t)(b * NH + h) * S_LEN + qt * 128) * HD;
        const __nv_bfloat16* q1 = g_Ql + ((size_t)(b * NH + h) * S_LEN + qt * 128) * HD;
#pragma unroll
        for (int u = 0; u < 8; u++) {
            int id = t + u * 256;            // 2048 ids: 128 rows x 16 chunks
            int row = id >> 4, ch = id & 15;
            uint32_t d = row * AQ_PITCH + ch * 16;
            CP_ASYNC16(sQh + d, q0 + (size_t)row * HD + ch * 8);
            CP_ASYNC16(sQl + d, q1 + (size_t)row * HD + ch * 8);
        }
        CP_COMMIT();
    }

    float acc[16][4];
#pragma unroll
    for (int n = 0; n < 16; n++)
#pragma unroll
        for (int c = 0; c < 4; c++) acc[n][c] = 0.f;
    float m0 = -1e30f, m1 = -1e30f, l0 = 0.f, l1 = 0.f;

    const __nv_bfloat16* kb0 = g_Kh + ((size_t)(b * NKV + kh) * S_LEN) * HD;
    const __nv_bfloat16* kb1 = g_Kl + ((size_t)(b * NKV + kh) * S_LEN) * HD;
    const __nv_bfloat16* vb0 = g_Vh + ((size_t)(b * NKV + kh) * HD) * S_LEN;
    const __nv_bfloat16* vb1 = g_Vl + ((size_t)(b * NKV + kh) * HD) * S_LEN;
    const float SC = 0.08838834764831843f;

    const int nkt = 2 * qt + 2;
    for (int kt = 0; kt < nkt; kt++) {
        __syncthreads();   // prior iteration done reading K/V smem

        // ---- load K (64x128) and V^T (128x64) hi/lo ----
#pragma unroll
        for (int u = 0; u < 4; u++) {
            int id = t + u * 256;            // 1024: 64 rows x 16 chunks
            int row = id >> 4, ch = id & 15;
            uint32_t d = row * AK_PITCH + ch * 16;
            const size_t go = (size_t)(kt * 64 + row) * HD + ch * 8;
            CP_ASYNC16(sKh + d, kb0 + go);
            CP_ASYNC16(sKl + d, kb1 + go);
        }
#pragma unroll
        for (int u = 0; u < 4; u++) {
            int id = t + u * 256;            // 1024: 128 rows x 8 chunks
            int row = id >> 3, ch = id & 7;
            uint32_t d = row * AV_PITCH + ch * 16;
            const size_t go = (size_t)row * S_LEN + kt * 64 + ch * 8;
            CP_ASYNC16(sVh + d, vb0 + go);
            CP_ASYNC16(sVl + d, vb1 + go);
        }
        CP_COMMIT();
        CP_WAIT(0);
        __syncthreads();

        // ---- scores: S = Q K^T (64 cols), 3-product split ----
        float s[8][4];
#pragma unroll
        for (int n = 0; n < 8; n++)
#pragma unroll
            for (int c = 0; c < 4; c++) s[n][c] = 0.f;

#pragma unroll
        for (int dc = 0; dc < 8; dc++) {
            const int k0b = dc * 32;
            uint32_t ah[4], al[4];
            uint32_t qa = sQh + (uint32_t)(wm + (lane & 15)) * AQ_PITCH + k0b + ((lane >> 4) << 4);
            LDSM_X4(ah, qa);
            LDSM_X4(al, qa + SQ_BYTES);
            uint32_t bh[4][4], bl[4][4];
#pragma unroll
            for (int p = 0; p < 4; p++) {
                uint32_t ka = sKh + (uint32_t)(p * 16 + ((lane >> 4) << 3) + (lane & 7)) * AK_PITCH
                            + k0b + (((lane >> 3) & 1) << 4);
                LDSM_X4(bh[p], ka);
                LDSM_X4(bl[p], ka + SK_BYTES);
            }
#pragma unroll
            for (int nt = 0; nt < 8; nt++) {
                const int p = nt >> 1, hh = (nt & 1) * 2;
                MMA16816(s[nt], ah, bh[p][hh], bh[p][hh + 1]);
                MMA16816(s[nt], ah, bl[p][hh], bl[p][hh + 1]);
                MMA16816(s[nt], al, bh[p][hh], bh[p][hh + 1]);
            }
        }

        // ---- scale + causal mask (only last two kt tiles need masking) ----
        if (kt >= 2 * qt) {
            const int gr0 = qt * 128 + wm + (lane >> 2);
#pragma unroll
            for (int nt = 0; nt < 8; nt++)
#pragma unroll
                for (int c = 0; c < 4; c++) {
                    int gc = kt * 64 + nt * 8 + ((lane & 3) << 1) + (c & 1);
                    int gr = gr0 + ((c >> 1) << 3);
                    s[nt][c] = (gc > gr) ? -1e30f : s[nt][c] * SC;
                }
        } else {
#pragma unroll
            for (int nt = 0; nt < 8; nt++)
#pragma unroll
                for (int c = 0; c < 4; c++) s[nt][c] *= SC;
        }

        // ---- online softmax (two rows per thread; quad shfl) ----
        float mt0 = -1e30f, mt1 = -1e30f;
#pragma unroll
        for (int nt = 0; nt < 8; nt++) {
            mt0 = fmaxf(mt0, fmaxf(s[nt][0], s[nt][1]));
            mt1 = fmaxf(mt1, fmaxf(s[nt][2], s[nt][3]));
        }
        mt0 = fmaxf(mt0, __shfl_xor_sync(0xffffffffu, mt0, 1));
        mt0 = fmaxf(mt0, __shfl_xor_sync(0xffffffffu, mt0, 2));
        mt1 = fmaxf(mt1, __shfl_xor_sync(0xffffffffu, mt1, 1));
        mt1 = fmaxf(mt1, __shfl_xor_sync(0xffffffffu, mt1, 2));
        float mn0 = fmaxf(m0, mt0), mn1 = fmaxf(m1, mt1);
        float sc0 = __expf(m0 - mn0), sc1 = __expf(m1 - mn1);
        float rs0 = 0.f, rs1 = 0.f;
#pragma unroll
        for (int nt = 0; nt < 8; nt++) {
            s[nt][0] = __expf(s[nt][0] - mn0);
            s[nt][1] = __expf(s[nt][1] - mn0);
            s[nt][2] = __expf(s[nt][2] - mn1);
            s[nt][3] = __expf(s[nt][3] - mn1);
            rs0 += s[nt][0] + s[nt][1];
            rs1 += s[nt][2] + s[nt][3];
        }
        rs0 += __shfl_xor_sync(0xffffffffu, rs0, 1);
        rs0 += __shfl_xor_sync(0xffffffffu, rs0, 2);
        rs1 += __shfl_xor_sync(0xffffffffu, rs1, 1);
        rs1 += __shfl_xor_sync(0xffffffffu, rs1, 2);
        l0 = l0 * sc0 + rs0;  m0 = mn0;
        l1 = l1 * sc1 + rs1;  m1 = mn1;
#pragma unroll
        for (int n = 0; n < 16; n++) {
            acc[n][0] *= sc0;  acc[n][1] *= sc0;
            acc[n][2] *= sc1;  acc[n][3] *= sc1;
        }

        // ---- PV: O += P V ; P fragments built in place (FA2 layout identity) --
#pragma unroll
        for (int kc = 0; kc < 4; kc++) {
            uint32_t ph[4], pl[4];
            split2(s[2 * kc][0],     s[2 * kc][1],     ph[0], pl[0]);
            split2(s[2 * kc][2],     s[2 * kc][3],     ph[1], pl[1]);
            split2(s[2 * kc + 1][0], s[2 * kc + 1][1], ph[2], pl[2]);
            split2(s[2 * kc + 1][2], s[2 * kc + 1][3], ph[3], pl[3]);
#pragma unroll
            for (int dp = 0; dp < 8; dp++) {
                uint32_t vh4[4], vl4[4];
                uint32_t va = sVh + (uint32_t)(dp * 16 + ((lane >> 4) << 3) + (lane & 7)) * AV_PITCH
                            + kc * 32 + (((lane >> 3) & 1) << 4);
                LDSM_X4(vh4, va);
                LDSM_X4(vl4, va + SV_BYTES);
#pragma unroll
                for (int sub = 0; sub < 2; sub++) {
                    const int nt = dp * 2 + sub, hh = sub * 2;
                    MMA16816(acc[nt], ph, vh4[hh], vh4[hh + 1]);
                    MMA16816(acc[nt], ph, vl4[hh], vl4[hh + 1]);
                    MMA16816(acc[nt], pl, vh4[hh], vh4[hh + 1]);
                }
            }
        }
    }

    // ---- epilogue: normalize, split to bf16 hi/lo, write [b*S+s][h*128+d] ----
    const float inv0 = 1.0f / l0, inv1 = 1.0f / l1;
    const size_t row0 = (size_t)(b * S_LEN + qt * 128 + wm + (lane >> 2));
    const int colb = h * HD + ((lane & 3) << 1);
#pragma unroll
    for (int nt = 0; nt < 16; nt++) {
        uint32_t h0, lo0, h1, lo1;
        split2(acc[nt][0] * inv0, acc[nt][1] * inv0, h0, lo0);
        split2(acc[nt][2] * inv1, acc[nt][3] * inv1, h1, lo1);
        const size_t o0 = row0 * HID + colb + nt * 8;
        const size_t o1 = (row0 + 8) * HID + colb + nt * 8;
        *(uint32_t*)(Ohi + o0) = h0;
        *(uint32_t*)(Olo + o0) = lo0;
        *(uint32_t*)(Ohi + o1) = h1;
        *(uint32_t*)(Olo + o1) = lo1;
    }
}

// ---------------- launch ------------------------------------------------------
extern "C" void kernel_launch(void* const* d_in, const int* in_sizes, int n_in,
                              void* d_out, int out_size)
{
    const int*   positions = (const int*)  d_in[0];
    const float* hidden    = (const float*)d_in[1];
    const float* w_qkv     = (const float*)d_in[2];
    const float* w_o       = (const float*)d_in[3];
    float*       out       = (float*)d_out;

    static float* qkv_p;
    static __nv_bfloat16 *ahi, *alo, *bqh, *bql, *boh, *bol;
    static bool init_done = false;
    if (!init_done) {
        cudaGetSymbolAddress((void**)&qkv_p, g_qkv);
        cudaGetSymbolAddress((void**)&ahi, g_Ahi);
        cudaGetSymbolAddress((void**)&alo, g_Alo);
        cudaGetSymbolAddress((void**)&bqh, g_Bqh);
        cudaGetSymbolAddress((void**)&bql, g_Bql);
        cudaGetSymbolAddress((void**)&boh, g_Boh);
        cudaGetSymbolAddress((void**)&bol, g_Bol);
        cudaFuncSetAttribute(gemm_mma_kernel,
                             cudaFuncAttributeMaxDynamicSharedMemorySize, GEMM_SMEM_BYTES);
        cudaFuncSetAttribute(attn_mma_kernel,
                             cudaFuncAttributeMaxDynamicSharedMemorySize, ATT_SMEM_BYTES);
        init_done = true;
    }

    const int M = BATCH * S_LEN;   // 4096

    init_invfreq_kernel<<<1, 64>>>();

    // prep: split hidden, transpose+split weights
    split_a_kernel<<<(M * KDIM / 4 + 255) / 256, 256>>>(hidden, ahi, alo, M * KDIM / 4);
    transpose_split_kernel<<<dim3(QKVN / 32, KDIM / 32), 256>>>(w_qkv, bqh, bql, KDIM, QKVN);
    transpose_split_kernel<<<dim3(HID / 32, KDIM / 32), 256>>>(w_o, boh, bol, KDIM, HID);

    // qkv = hidden @ w_qkv
    gemm_mma_kernel<<<dim3(QKVN / 128, M / 128), 256, GEMM_SMEM_BYTES>>>(
        ahi, alo, bqh, bql, qkv_p, QKVN);

    // rope + split Q/K; transpose + split V
    rope_split_kernel<<<(BATCH * 40 * S_LEN * 64) / 256, 256>>>(qkv_p, positions);
    v_split_kernel<<<dim3(S_LEN / 32, HD / 32, BATCH * NKV), 256>>>(qkv_p);

    // flash attention (tensor cores); writes bf16 hi/lo directly into GEMM-A bufs
    attn_mma_kernel<<<dim3(S_LEN / 128, NH, BATCH), 256, ATT_SMEM_BYTES>>>(ahi, alo);

    // out = attn @ w_o
    gemm_mma_kernel<<<dim3(HID / 128, M / 128), 256, GEMM_SMEM_BYTES>>>(
        ahi, alo, boh, bol, out, HID);
}

// round 10
// speedup vs baseline: 2.7200x; 1.1275x over previous
#include <cuda_runtime.h>
#include <cuda_bf16.h>
#include <cstdint>
#include <math.h>

#define BATCH 2
#define S_LEN 2048
#define HID   4096
#define NH    32
#define NKV   8
#define HD    128
#define QKVN  6144          // Q 4096 | K 1024 | V 1024
#define VOFF  5120          // Q_SIZE + KV_SIZE
#define KDIM  4096          // GEMM K (reduction) for both projections

// ---------------- scratch (no allocation allowed -> device globals) ----------
__device__ float g_qkv [BATCH * S_LEN * QKVN];      // qkv projection output (fp32)
__device__ float g_invfreq[64];

// bf16 split operands for the tensor-core GEMMs
__device__ __nv_bfloat16 g_Ahi [4096 * 4096];       // A hi (hidden; then attn out)
__device__ __nv_bfloat16 g_Alo [4096 * 4096];       // A lo
__device__ __nv_bfloat16 g_Bqh [QKVN * 4096];       // w_qkv^T hi  [N=6144][K=4096]
__device__ __nv_bfloat16 g_Bql [QKVN * 4096];       // w_qkv^T lo
__device__ __nv_bfloat16 g_Boh [4096 * 4096];       // w_o^T hi    [N=4096][K=4096]
__device__ __nv_bfloat16 g_Bol [4096 * 4096];       // w_o^T lo

// bf16 split attention operands
__device__ __nv_bfloat16 g_Qh [BATCH * NH  * S_LEN * HD];  // [b][h][s][d]
__device__ __nv_bfloat16 g_Ql [BATCH * NH  * S_LEN * HD];
__device__ __nv_bfloat16 g_Kh [BATCH * NKV * S_LEN * HD];  // [b][kh][s][d]
__device__ __nv_bfloat16 g_Kl [BATCH * NKV * S_LEN * HD];
__device__ __nv_bfloat16 g_Vh [BATCH * NKV * HD * S_LEN];  // [b][kh][d][s]
__device__ __nv_bfloat16 g_Vl [BATCH * NKV * HD * S_LEN];

// ================= helpers ====================================================
__device__ __forceinline__ uint32_t smem_u32(const void* p) {
    uint32_t a;
    asm("{ .reg .u64 t; cvta.to.shared.u64 t, %1; cvt.u32.u64 %0, t; }" : "=r"(a) : "l"(p));
    return a;
}

#define LDSM_X4(r, addr) \
    asm volatile("ldmatrix.sync.aligned.m8n8.x4.shared.b16 {%0,%1,%2,%3}, [%4];" \
        : "=r"((r)[0]), "=r"((r)[1]), "=r"((r)[2]), "=r"((r)[3]) : "r"(addr))

#define MMA16816(c, a, b0, b1) \
    asm volatile("mma.sync.aligned.m16n8k16.row.col.f32.bf16.bf16.f32 " \
        "{%0,%1,%2,%3}, {%4,%5,%6,%7}, {%8,%9}, {%0,%1,%2,%3};" \
        : "+f"((c)[0]), "+f"((c)[1]), "+f"((c)[2]), "+f"((c)[3]) \
        : "r"((a)[0]), "r"((a)[1]), "r"((a)[2]), "r"((a)[3]), "r"(b0), "r"(b1))

#define CP_ASYNC16(dst, src) \
    asm volatile("cp.async.cg.shared.global [%0], [%1], 16;" :: "r"(dst), "l"(src))
#define CP_COMMIT() asm volatile("cp.async.commit_group;" ::: "memory")
#define CP_WAIT(n)  asm volatile("cp.async.wait_group %0;" :: "n"(n) : "memory")

__device__ __forceinline__ void split2(float a, float b, uint32_t& hi, uint32_t& lo) {
    __nv_bfloat16 ha = __float2bfloat16(a), hb = __float2bfloat16(b);
    __nv_bfloat16 la = __float2bfloat16(a - __bfloat162float(ha));
    __nv_bfloat16 lb = __float2bfloat16(b - __bfloat162float(hb));
    __nv_bfloat162 H = __halves2bfloat162(ha, hb);
    __nv_bfloat162 L = __halves2bfloat162(la, lb);
    hi = *(uint32_t*)&H;  lo = *(uint32_t*)&L;
}

extern __shared__ char dynsmem[];

// ---------------- inv_freq table ---------------------------------------------
__global__ void init_invfreq_kernel() {
    int i = threadIdx.x;
    if (i < 64) {
        const float LOG2_10000 = 13.28771237954945f;
        g_invfreq[i] = exp2f(-((float)(2 * i) / 128.0f) * LOG2_10000);
    }
}

// ---------------- fp32 -> bf16 hi/lo split (elementwise, float4) --------------
__global__ void __launch_bounds__(256) split_a_kernel(
    const float* __restrict__ X, __nv_bfloat16* __restrict__ hi,
    __nv_bfloat16* __restrict__ lo, int n4)
{
    int i = blockIdx.x * 256 + threadIdx.x;
    if (i >= n4) return;
    float4 v = ((const float4*)X)[i];
    uint32_t h0, l0, h1, l1;
    split2(v.x, v.y, h0, l0);
    split2(v.z, v.w, h1, l1);
    ((uint32_t*)hi)[i * 2]     = h0;
    ((uint32_t*)hi)[i * 2 + 1] = h1;
    ((uint32_t*)lo)[i * 2]     = l0;
    ((uint32_t*)lo)[i * 2 + 1] = l1;
}

// ---------------- W[K,N] fp32 -> Bt[N,K] bf16 hi/lo (tiled transpose) ---------
__global__ void __launch_bounds__(256) transpose_split_kernel(
    const float* __restrict__ W, __nv_bfloat16* __restrict__ bhi,
    __nv_bfloat16* __restrict__ blo, int K, int N)
{
    __shared__ float tile[32][33];
    int tx = threadIdx.x & 31, ty = threadIdx.x >> 5;   // 32 x 8
    int k0 = blockIdx.y * 32, n0 = blockIdx.x * 32;
#pragma unroll
    for (int r = 0; r < 4; r++)
        tile[ty + r * 8][tx] = W[(size_t)(k0 + ty + r * 8) * N + n0 + tx];
    __syncthreads();
#pragma unroll
    for (int r = 0; r < 4; r++) {
        int n = n0 + ty + r * 8;
        int k = k0 + tx;
        float x = tile[tx][ty + r * 8];
        __nv_bfloat16 h = __float2bfloat16(x);
        __nv_bfloat16 l = __float2bfloat16(x - __bfloat162float(h));
        bhi[(size_t)n * K + k] = h;
        blo[(size_t)n * K + k] = l;
    }
}

// ---------------- mma.sync split-bf16 GEMM (now 2 CTAs/SM) --------------------
#define GPITCH 80
#define GTSZ   (128 * GPITCH)
#define GSTG   (4 * GTSZ)
#define GEMM_SMEM_BYTES (2 * GSTG)     // 81920 -> 2 CTAs = 163840 <= 228KB

__global__ void __launch_bounds__(256, 2) gemm_mma_kernel(
    const __nv_bfloat16* __restrict__ Ahi, const __nv_bfloat16* __restrict__ Alo,
    const __nv_bfloat16* __restrict__ Bhi, const __nv_bfloat16* __restrict__ Blo,
    float* __restrict__ C, int Ntot)
{
    const uint32_t sb = smem_u32(dynsmem);
    const int t = threadIdx.x;
    const int wid = t >> 5, lane = t & 31;
    const int bm = blockIdx.y, bn = blockIdx.x;
    const int wm = (wid >> 2) * 64;
    const int wn = (wid & 3) * 32;

    const __nv_bfloat16* gsrc[4] = {
        Ahi + (size_t)(bm * 128) * KDIM,
        Alo + (size_t)(bm * 128) * KDIM,
        Bhi + (size_t)(bn * 128) * KDIM,
        Blo + (size_t)(bn * 128) * KDIM };

    const int lrow = t >> 1;
    const int lq   = (t & 1) * 2;

    auto load_chunk = [&](int c, int s) {
        uint32_t base = sb + s * GSTG + lrow * GPITCH + lq * 16;
#pragma unroll
        for (int tens = 0; tens < 4; tens++) {
            const __nv_bfloat16* src = gsrc[tens] + (size_t)lrow * KDIM + c * 32 + lq * 8;
            uint32_t d = base + tens * GTSZ;
            CP_ASYNC16(d, src);
            CP_ASYNC16(d + 16, src + 8);
        }
    };

    float acc[4][4][4];
#pragma unroll
    for (int a = 0; a < 4; a++)
#pragma unroll
        for (int b = 0; b < 4; b++)
#pragma unroll
            for (int c = 0; c < 4; c++) acc[a][b][c] = 0.f;

    const int NCH = KDIM / 32;

    load_chunk(0, 0);
    CP_COMMIT();

    for (int i = 0; i < NCH; i++) {
        const int s = i & 1;
        if (i + 1 < NCH) {
            load_chunk(i + 1, (i + 1) & 1);
            CP_COMMIT();
            CP_WAIT(1);
        } else {
            CP_WAIT(0);
        }
        __syncthreads();

        const uint32_t sA = sb + s * GSTG;
        const uint32_t sB = sA + 2 * GTSZ;

#pragma unroll
        for (int ks = 0; ks < 2; ks++) {
            const int k0b = ks * 32;
            // B fragments first (stay live across the mt loop)
            uint32_t b_hi[2][4], b_lo[2][4];
#pragma unroll
            for (int p = 0; p < 2; p++) {
                uint32_t bd = sB + (uint32_t)(wn + p * 16 + ((lane >> 4) << 3) + (lane & 7)) * GPITCH
                            + k0b + (((lane >> 3) & 1) << 4);
                LDSM_X4(b_hi[p], bd);
                LDSM_X4(b_lo[p], bd + GTSZ);
            }
            // A fragments loaded per-mt (short live range -> fewer registers)
#pragma unroll
            for (int mt = 0; mt < 4; mt++) {
                uint32_t ah[4], al[4];
                uint32_t ad = sA + (uint32_t)(wm + mt * 16 + (lane & 15)) * GPITCH
                            + k0b + ((lane >> 4) << 4);
                LDSM_X4(ah, ad);
                LDSM_X4(al, ad + GTSZ);
#pragma unroll
                for (int nt = 0; nt < 4; nt++) {
                    const int p = nt >> 1, hh = (nt & 1) * 2;
                    MMA16816(acc[mt][nt], ah, b_hi[p][hh], b_hi[p][hh + 1]);
                    MMA16816(acc[mt][nt], ah, b_lo[p][hh], b_lo[p][hh + 1]);
                    MMA16816(acc[mt][nt], al, b_hi[p][hh], b_hi[p][hh + 1]);
                }
            }
        }
        __syncthreads();
    }

#pragma unroll
    for (int mt = 0; mt < 4; mt++)
#pragma unroll
        for (int nt = 0; nt < 4; nt++) {
            int row = bm * 128 + wm + mt * 16 + (lane >> 2);
            int col = bn * 128 + wn + nt * 8 + (lane & 3) * 2;
            float2 v0 = make_float2(acc[mt][nt][0], acc[mt][nt][1]);
            float2 v1 = make_float2(acc[mt][nt][2], acc[mt][nt][3]);
            *(float2*)(C + (size_t)row * Ntot + col)       = v0;
            *(float2*)(C + (size_t)(row + 8) * Ntot + col) = v1;
        }
}

// ---------------- RoPE (NeoX) + bf16 hi/lo split, natural [.,s,d] layout ------
__global__ void rope_split_kernel(const float* __restrict__ qkv,
                                  const int*   __restrict__ positions)
{
    int idx = blockIdx.x * 256 + threadIdx.x;
    int i  = idx & 63;
    int s  = (idx >> 6) & (S_LEN - 1);
    int r  = idx >> 17;          // b*40 + hh
    int hh = r % 40;
    int b  = r / 40;

    float pos = (float)positions[b * S_LEN + s];
    float ang = pos * g_invfreq[i];
    float sn, cs;
    sincosf(ang, &sn, &cs);

    if (hh < 32) {
        const float* src = qkv + ((size_t)(b * S_LEN + s)) * QKVN + hh * HD;
        float x1 = src[i], x2 = src[i + 64];
        float y1 = x1 * cs - x2 * sn;
        float y2 = x2 * cs + x1 * sn;
        size_t base = ((size_t)(b * NH + hh) * S_LEN + s) * HD;
        __nv_bfloat16 h1 = __float2bfloat16(y1);
        __nv_bfloat16 h2 = __float2bfloat16(y2);
        g_Qh[base + i]      = h1;
        g_Qh[base + i + 64] = h2;
        g_Ql[base + i]      = __float2bfloat16(y1 - __bfloat162float(h1));
        g_Ql[base + i + 64] = __float2bfloat16(y2 - __bfloat162float(h2));
    } else {
        int kh = hh - 32;
        const float* src = qkv + ((size_t)(b * S_LEN + s)) * QKVN + HID + kh * HD;
        float x1 = src[i], x2 = src[i + 64];
        float y1 = x1 * cs - x2 * sn;
        float y2 = x2 * cs + x1 * sn;
        size_t base = ((size_t)(b * NKV + kh) * S_LEN + s) * HD;
        __nv_bfloat16 h1 = __float2bfloat16(y1);
        __nv_bfloat16 h2 = __float2bfloat16(y2);
        g_Kh[base + i]      = h1;
        g_Kh[base + i + 64] = h2;
        g_Kl[base + i]      = __float2bfloat16(y1 - __bfloat162float(h1));
        g_Kl[base + i + 64] = __float2bfloat16(y2 - __bfloat162float(h2));
    }
}

// ---------------- V: [s][d] fp32 -> [d][s] bf16 hi/lo (tiled transpose) -------
__global__ void __launch_bounds__(256) v_split_kernel(const float* __restrict__ qkv)
{
    __shared__ float tile[32][33];
    int tx = threadIdx.x & 31, ty = threadIdx.x >> 5;   // 32 x 8
    int s0 = blockIdx.x * 32, d0 = blockIdx.y * 32;
    int slab = blockIdx.z;                               // b*NKV + kh
    int b = slab / NKV, kh = slab % NKV;

    const float* src = qkv + (size_t)(b * S_LEN) * QKVN + VOFF + kh * HD;
#pragma unroll
    for (int r = 0; r < 4; r++)
        tile[ty + r * 8][tx] = src[(size_t)(s0 + ty + r * 8) * QKVN + d0 + tx];
    __syncthreads();
#pragma unroll
    for (int r = 0; r < 4; r++) {
        int d = d0 + ty + r * 8;
        int s = s0 + tx;
        float x = tile[tx][ty + r * 8];
        __nv_bfloat16 h = __float2bfloat16(x);
        __nv_bfloat16 l = __float2bfloat16(x - __bfloat162float(h));
        size_t o = ((size_t)(b * NKV + kh) * HD + d) * S_LEN + s;
        g_Vh[o] = h;
        g_Vl[o] = l;
    }
}

// ---------------- mma.sync split-bf16 flash attention (2-stage K/V pipe) ------
#define AQ_PITCH 272     // 256B row + 16B pad
#define AK_PITCH 272
#define AV_PITCH 144     // 128B row + 16B pad
#define SQ_BYTES (128 * AQ_PITCH)            // 34816
#define SK_BYTES (64  * AK_PITCH)            // 17408
#define SV_BYTES (128 * AV_PITCH)            // 18432
#define KV_STG   (2 * SK_BYTES + 2 * SV_BYTES)   // 71680 per stage
#define ATT_SMEM_BYTES (2 * SQ_BYTES + 2 * KV_STG)  // 212992

__global__ void __launch_bounds__(256, 1) attn_mma_kernel(
    __nv_bfloat16* __restrict__ Ohi, __nv_bfloat16* __restrict__ Olo)
{
    const int qt = blockIdx.x;      // 0..15 (128-row tiles)
    const int h  = blockIdx.y;
    const int b  = blockIdx.z;
    const int kh = h >> 2;

    const uint32_t sb  = smem_u32(dynsmem);
    const uint32_t sQh = sb;
    const uint32_t sQl = sQh + SQ_BYTES;
    const uint32_t sKV = sQl + SQ_BYTES;     // stage base: + s*KV_STG
    // within a stage: Kh @0, Kl @SK, Vh @2*SK, Vl @2*SK+SV

    const int t = threadIdx.x;
    const int wid = t >> 5, lane = t & 31;
    const int wm = wid * 16;

    const __nv_bfloat16* kb0 = g_Kh + ((size_t)(b * NKV + kh) * S_LEN) * HD;
    const __nv_bfloat16* kb1 = g_Kl + ((size_t)(b * NKV + kh) * S_LEN) * HD;
    const __nv_bfloat16* vb0 = g_Vh + ((size_t)(b * NKV + kh) * HD) * S_LEN;
    const __nv_bfloat16* vb1 = g_Vl + ((size_t)(b * NKV + kh) * HD) * S_LEN;

    auto load_kv = [&](int kt, int s) {
        const uint32_t st = sKV + s * KV_STG;
#pragma unroll
        for (int u = 0; u < 4; u++) {
            int id = t + u * 256;            // 1024: 64 rows x 16 chunks
            int row = id >> 4, ch = id & 15;
            uint32_t d = row * AK_PITCH + ch * 16;
            const size_t go = (size_t)(kt * 64 + row) * HD + ch * 8;
            CP_ASYNC16(st + d, kb0 + go);
            CP_ASYNC16(st + SK_BYTES + d, kb1 + go);
        }
#pragma unroll
        for (int u = 0; u < 4; u++) {
            int id = t + u * 256;            // 1024: 128 rows x 8 chunks
            int row = id >> 3, ch = id & 7;
            uint32_t d = row * AV_PITCH + ch * 16;
            const size_t go = (size_t)row * S_LEN + kt * 64 + ch * 8;
            CP_ASYNC16(st + 2 * SK_BYTES + d, vb0 + go);
            CP_ASYNC16(st + 2 * SK_BYTES + SV_BYTES + d, vb1 + go);
        }
    };

    // ---- load Q tile (once) ----
    {
        const __nv_bfloat16* q0 = g_Qh + ((size_t)(b * NH + h) * S_LEN + qt * 128) * HD;
        const __nv_bfloat16* q1 = g_Ql + ((size_t)(b * NH + h) * S_LEN + qt * 128) * HD;
#pragma unroll
        for (int u = 0; u < 8; u++) {
            int id = t + u * 256;            // 2048 ids: 128 rows x 16 chunks
            int row = id >> 4, ch = id & 15;
            uint32_t d = row * AQ_PITCH + ch * 16;
            CP_ASYNC16(sQh + d, q0 + (size_t)row * HD + ch * 8);
            CP_ASYNC16(sQl + d, q1 + (size_t)row * HD + ch * 8);
        }
        CP_COMMIT();
    }

    float acc[16][4];
#pragma unroll
    for (int n = 0; n < 16; n++)
#pragma unroll
        for (int c = 0; c < 4; c++) acc[n][c] = 0.f;
    float m0 = -1e30f, m1 = -1e30f, l0 = 0.f, l1 = 0.f;

    const float SC = 0.08838834764831843f;
    const int nkt = 2 * qt + 2;

    load_kv(0, 0);
    CP_COMMIT();

    for (int kt = 0; kt < nkt; kt++) {
        const int s = kt & 1;
        if (kt + 1 < nkt) {
            load_kv(kt + 1, s ^ 1);
            CP_COMMIT();
            CP_WAIT(1);
        } else {
            CP_WAIT(0);
        }
        __syncthreads();

        const uint32_t sKh = sKV + s * KV_STG;
        const uint32_t sKl = sKh + SK_BYTES;
        const uint32_t sVh = sKh + 2 * SK_BYTES;
        const uint32_t sVl = sVh + SV_BYTES;

        // ---- scores: S = Q K^T (64 cols), 3-product split ----
        float sc4[8][4];
#pragma unroll
        for (int n = 0; n < 8; n++)
#pragma unroll
            for (int c = 0; c < 4; c++) sc4[n][c] = 0.f;

#pragma unroll
        for (int dc = 0; dc < 8; dc++) {
            const int k0b = dc * 32;
            uint32_t ah[4], al[4];
            uint32_t qa = sQh + (uint32_t)(wm + (lane & 15)) * AQ_PITCH + k0b + ((lane >> 4) << 4);
            LDSM_X4(ah, qa);
            LDSM_X4(al, qa + SQ_BYTES);
            uint32_t bh[4][4], bl[4][4];
#pragma unroll
            for (int p = 0; p < 4; p++) {
                uint32_t ka = sKh + (uint32_t)(p * 16 + ((lane >> 4) << 3) + (lane & 7)) * AK_PITCH
                            + k0b + (((lane >> 3) & 1) << 4);
                LDSM_X4(bh[p], ka);
                LDSM_X4(bl[p], ka + SK_BYTES);
            }
#pragma unroll
            for (int nt = 0; nt < 8; nt++) {
                const int p = nt >> 1, hh = (nt & 1) * 2;
                MMA16816(sc4[nt], ah, bh[p][hh], bh[p][hh + 1]);
                MMA16816(sc4[nt], ah, bl[p][hh], bl[p][hh + 1]);
                MMA16816(sc4[nt], al, bh[p][hh], bh[p][hh + 1]);
            }
        }

        // ---- scale + causal mask (only last two kt tiles need masking) ----
        if (kt >= 2 * qt) {
            const int gr0 = qt * 128 + wm + (lane >> 2);
#pragma unroll
            for (int nt = 0; nt < 8; nt++)
#pragma unroll
                for (int c = 0; c < 4; c++) {
                    int gc = kt * 64 + nt * 8 + ((lane & 3) << 1) + (c & 1);
                    int gr = gr0 + ((c >> 1) << 3);
                    sc4[nt][c] = (gc > gr) ? -1e30f : sc4[nt][c] * SC;
                }
        } else {
#pragma unroll
            for (int nt = 0; nt < 8; nt++)
#pragma unroll
                for (int c = 0; c < 4; c++) sc4[nt][c] *= SC;
        }

        // ---- online softmax (two rows per thread; quad shfl) ----
        float mt0 = -1e30f, mt1 = -1e30f;
#pragma unroll
        for (int nt = 0; nt < 8; nt++) {
            mt0 = fmaxf(mt0, fmaxf(sc4[nt][0], sc4[nt][1]));
            mt1 = fmaxf(mt1, fmaxf(sc4[nt][2], sc4[nt][3]));
        }
        mt0 = fmaxf(mt0, __shfl_xor_sync(0xffffffffu, mt0, 1));
        mt0 = fmaxf(mt0, __shfl_xor_sync(0xffffffffu, mt0, 2));
        mt1 = fmaxf(mt1, __shfl_xor_sync(0xffffffffu, mt1, 1));
        mt1 = fmaxf(mt1, __shfl_xor_sync(0xffffffffu, mt1, 2));
        float mn0 = fmaxf(m0, mt0), mn1 = fmaxf(m1, mt1);
        float es0 = __expf(m0 - mn0), es1 = __expf(m1 - mn1);
        float rs0 = 0.f, rs1 = 0.f;
#pragma unroll
        for (int nt = 0; nt < 8; nt++) {
            sc4[nt][0] = __expf(sc4[nt][0] - mn0);
            sc4[nt][1] = __expf(sc4[nt][1] - mn0);
            sc4[nt][2] = __expf(sc4[nt][2] - mn1);
            sc4[nt][3] = __expf(sc4[nt][3] - mn1);
            rs0 += sc4[nt][0] + sc4[nt][1];
            rs1 += sc4[nt][2] + sc4[nt][3];
        }
        rs0 += __shfl_xor_sync(0xffffffffu, rs0, 1);
        rs0 += __shfl_xor_sync(0xffffffffu, rs0, 2);
        rs1 += __shfl_xor_sync(0xffffffffu, rs1, 1);
        rs1 += __shfl_xor_sync(0xffffffffu, rs1, 2);
        l0 = l0 * es0 + rs0;  m0 = mn0;
        l1 = l1 * es1 + rs1;  m1 = mn1;
#pragma unroll
        for (int n = 0; n < 16; n++) {
            acc[n][0] *= es0;  acc[n][1] *= es0;
            acc[n][2] *= es1;  acc[n][3] *= es1;
        }

        // ---- PV: O += P V ; P fragments built in place (FA2 layout identity) --
#pragma unroll
        for (int kc = 0; kc < 4; kc++) {
            uint32_t ph[4], pl[4];
            split2(sc4[2 * kc][0],     sc4[2 * kc][1],     ph[0], pl[0]);
            split2(sc4[2 * kc][2],     sc4[2 * kc][3],     ph[1], pl[1]);
            split2(sc4[2 * kc + 1][0], sc4[2 * kc + 1][1], ph[2], pl[2]);
            split2(sc4[2 * kc + 1][2], sc4[2 * kc + 1][3], ph[3], pl[3]);
#pragma unroll
            for (int dp = 0; dp < 8; dp++) {
                uint32_t vh4[4], vl4[4];
                uint32_t va = sVh + (uint32_t)(dp * 16 + ((lane >> 4) << 3) + (lane & 7)) * AV_PITCH
                            + kc * 32 + (((lane >> 3) & 1) << 4);
                LDSM_X4(vh4, va);
                LDSM_X4(vl4, va + SV_BYTES);
#pragma unroll
                for (int sub = 0; sub < 2; sub++) {
                    const int nt = dp * 2 + sub, hh = sub * 2;
                    MMA16816(acc[nt], ph, vh4[hh], vh4[hh + 1]);
                    MMA16816(acc[nt], ph, vl4[hh], vl4[hh + 1]);
                    MMA16816(acc[nt], pl, vh4[hh], vh4[hh + 1]);
                }
            }
        }
        __syncthreads();   // done with stage s before next iteration reloads it
    }

    // ---- epilogue: normalize, split to bf16 hi/lo, write [b*S+s][h*128+d] ----
    const float inv0 = 1.0f / l0, inv1 = 1.0f / l1;
    const size_t row0 = (size_t)(b * S_LEN + qt * 128 + wm + (lane >> 2));
    const int colb = h * HD + ((lane & 3) << 1);
#pragma unroll
    for (int nt = 0; nt < 16; nt++) {
        uint32_t h0, lo0, h1, lo1;
        split2(acc[nt][0] * inv0, acc[nt][1] * inv0, h0, lo0);
        split2(acc[nt][2] * inv1, acc[nt][3] * inv1, h1, lo1);
        const size_t o0 = row0 * HID + colb + nt * 8;
        const size_t o1 = (row0 + 8) * HID + colb + nt * 8;
        *(uint32_t*)(Ohi + o0) = h0;
        *(uint32_t*)(Olo + o0) = lo0;
        *(uint32_t*)(Ohi + o1) = h1;
        *(uint32_t*)(Olo + o1) = lo1;
    }
}

// ---------------- launch ------------------------------------------------------
extern "C" void kernel_launch(void* const* d_in, const int* in_sizes, int n_in,
                              void* d_out, int out_size)
{
    const int*   positions = (const int*)  d_in[0];
    const float* hidden    = (const float*)d_in[1];
    const float* w_qkv     = (const float*)d_in[2];
    const float* w_o       = (const float*)d_in[3];
    float*       out       = (float*)d_out;

    static float* qkv_p;
    static __nv_bfloat16 *ahi, *alo, *bqh, *bql, *boh, *bol;
    static bool init_done = false;
    if (!init_done) {
        cudaGetSymbolAddress((void**)&qkv_p, g_qkv);
        cudaGetSymbolAddress((void**)&ahi, g_Ahi);
        cudaGetSymbolAddress((void**)&alo, g_Alo);
        cudaGetSymbolAddress((void**)&bqh, g_Bqh);
        cudaGetSymbolAddress((void**)&bql, g_Bql);
        cudaGetSymbolAddress((void**)&boh, g_Boh);
        cudaGetSymbolAddress((void**)&bol, g_Bol);
        cudaFuncSetAttribute(gemm_mma_kernel,
                             cudaFuncAttributeMaxDynamicSharedMemorySize, GEMM_SMEM_BYTES);
        cudaFuncSetAttribute(attn_mma_kernel,
                             cudaFuncAttributeMaxDynamicSharedMemorySize, ATT_SMEM_BYTES);
        init_done = true;
    }

    const int M = BATCH * S_LEN;   // 4096

    init_invfreq_kernel<<<1, 64>>>();

    // prep: split hidden, transpose+split weights
    split_a_kernel<<<(M * KDIM / 4 + 255) / 256, 256>>>(hidden, ahi, alo, M * KDIM / 4);
    transpose_split_kernel<<<dim3(QKVN / 32, KDIM / 32), 256>>>(w_qkv, bqh, bql, KDIM, QKVN);
    transpose_split_kernel<<<dim3(HID / 32, KDIM / 32), 256>>>(w_o, boh, bol, KDIM, HID);

    // qkv = hidden @ w_qkv
    gemm_mma_kernel<<<dim3(QKVN / 128, M / 128), 256, GEMM_SMEM_BYTES>>>(
        ahi, alo, bqh, bql, qkv_p, QKVN);

    // rope + split Q/K; transpose + split V
    rope_split_kernel<<<(BATCH * 40 * S_LEN * 64) / 256, 256>>>(qkv_p, positions);
    v_split_kernel<<<dim3(S_LEN / 32, HD / 32, BATCH * NKV), 256>>>(qkv_p);

    // flash attention (tensor cores); writes bf16 hi/lo directly into GEMM-A bufs
    attn_mma_kernel<<<dim3(S_LEN / 128, NH, BATCH), 256, ATT_SMEM_BYTES>>>(ahi, alo);

    // out = attn @ w_o
    gemm_mma_kernel<<<dim3(HID / 128, M / 128), 256, GEMM_SMEM_BYTES>>>(
        ahi, alo, boh, bol, out, HID);
}

// round 11
// speedup vs baseline: 2.7541x; 1.0125x over previous
#include <cuda_runtime.h>
#include <cuda_bf16.h>
#include <cstdint>
#include <math.h>

#define BATCH 2
#define S_LEN 2048
#define HID   4096
#define NH    32
#define NKV   8
#define HD    128
#define QKVN  6144          // Q 4096 | K 1024 | V 1024
#define VOFF  5120          // Q_SIZE + KV_SIZE
#define KDIM  4096          // GEMM K (reduction) for both projections

// ---------------- scratch (no allocation allowed -> device globals) ----------
__device__ float g_qkv [BATCH * S_LEN * QKVN];      // qkv projection output (fp32)
__device__ float g_invfreq[64];

// bf16 split operands for the tensor-core GEMMs
__device__ __nv_bfloat16 g_Ahi [4096 * 4096];       // A hi (hidden; then attn out)
__device__ __nv_bfloat16 g_Alo [4096 * 4096];       // A lo
__device__ __nv_bfloat16 g_Bqh [QKVN * 4096];       // w_qkv^T hi  [N=6144][K=4096]
__device__ __nv_bfloat16 g_Bql [QKVN * 4096];       // w_qkv^T lo
__device__ __nv_bfloat16 g_Boh [4096 * 4096];       // w_o^T hi    [N=4096][K=4096]
__device__ __nv_bfloat16 g_Bol [4096 * 4096];       // w_o^T lo

// bf16 split attention operands
__device__ __nv_bfloat16 g_Qh [BATCH * NH  * S_LEN * HD];  // [b][h][s][d]
__device__ __nv_bfloat16 g_Ql [BATCH * NH  * S_LEN * HD];
__device__ __nv_bfloat16 g_Kh [BATCH * NKV * S_LEN * HD];  // [b][kh][s][d]
__device__ __nv_bfloat16 g_Kl [BATCH * NKV * S_LEN * HD];
__device__ __nv_bfloat16 g_Vh [BATCH * NKV * HD * S_LEN];  // [b][kh][d][s]
__device__ __nv_bfloat16 g_Vl [BATCH * NKV * HD * S_LEN];

// ================= helpers ====================================================
__device__ __forceinline__ uint32_t smem_u32(const void* p) {
    uint32_t a;
    asm("{ .reg .u64 t; cvta.to.shared.u64 t, %1; cvt.u32.u64 %0, t; }" : "=r"(a) : "l"(p));
    return a;
}

#define LDSM_X4(r, addr) \
    asm volatile("ldmatrix.sync.aligned.m8n8.x4.shared.b16 {%0,%1,%2,%3}, [%4];" \
        : "=r"((r)[0]), "=r"((r)[1]), "=r"((r)[2]), "=r"((r)[3]) : "r"(addr))

#define MMA16816(c, a, b0, b1) \
    asm volatile("mma.sync.aligned.m16n8k16.row.col.f32.bf16.bf16.f32 " \
        "{%0,%1,%2,%3}, {%4,%5,%6,%7}, {%8,%9}, {%0,%1,%2,%3};" \
        : "+f"((c)[0]), "+f"((c)[1]), "+f"((c)[2]), "+f"((c)[3]) \
        : "r"((a)[0]), "r"((a)[1]), "r"((a)[2]), "r"((a)[3]), "r"(b0), "r"(b1))

#define CP_ASYNC16(dst, src) \
    asm volatile("cp.async.cg.shared.global [%0], [%1], 16;" :: "r"(dst), "l"(src))
#define CP_COMMIT() asm volatile("cp.async.commit_group;" ::: "memory")
#define CP_WAIT(n)  asm volatile("cp.async.wait_group %0;" :: "n"(n) : "memory")

__device__ __forceinline__ void split2(float a, float b, uint32_t& hi, uint32_t& lo) {
    __nv_bfloat16 ha = __float2bfloat16(a), hb = __float2bfloat16(b);
    __nv_bfloat16 la = __float2bfloat16(a - __bfloat162float(ha));
    __nv_bfloat16 lb = __float2bfloat16(b - __bfloat162float(hb));
    __nv_bfloat162 H = __halves2bfloat162(ha, hb);
    __nv_bfloat162 L = __halves2bfloat162(la, lb);
    hi = *(uint32_t*)&H;  lo = *(uint32_t*)&L;
}

extern __shared__ char dynsmem[];

// ---------------- inv_freq table ---------------------------------------------
__global__ void init_invfreq_kernel() {
    int i = threadIdx.x;
    if (i < 64) {
        const float LOG2_10000 = 13.28771237954945f;
        g_invfreq[i] = exp2f(-((float)(2 * i) / 128.0f) * LOG2_10000);
    }
}

// ---------------- fp32 -> bf16 hi/lo split (elementwise, float4) --------------
__global__ void __launch_bounds__(256) split_a_kernel(
    const float* __restrict__ X, __nv_bfloat16* __restrict__ hi,
    __nv_bfloat16* __restrict__ lo, int n4)
{
    int i = blockIdx.x * 256 + threadIdx.x;
    if (i >= n4) return;
    float4 v = ((const float4*)X)[i];
    uint32_t h0, l0, h1, l1;
    split2(v.x, v.y, h0, l0);
    split2(v.z, v.w, h1, l1);
    ((uint32_t*)hi)[i * 2]     = h0;
    ((uint32_t*)hi)[i * 2 + 1] = h1;
    ((uint32_t*)lo)[i * 2]     = l0;
    ((uint32_t*)lo)[i * 2 + 1] = l1;
}

// ---------------- W[K,N] fp32 -> Bt[N,K] bf16 hi/lo (tiled transpose) ---------
__global__ void __launch_bounds__(256) transpose_split_kernel(
    const float* __restrict__ W, __nv_bfloat16* __restrict__ bhi,
    __nv_bfloat16* __restrict__ blo, int K, int N)
{
    __shared__ float tile[32][33];
    int tx = threadIdx.x & 31, ty = threadIdx.x >> 5;   // 32 x 8
    int k0 = blockIdx.y * 32, n0 = blockIdx.x * 32;
#pragma unroll
    for (int r = 0; r < 4; r++)
        tile[ty + r * 8][tx] = W[(size_t)(k0 + ty + r * 8) * N + n0 + tx];
    __syncthreads();
#pragma unroll
    for (int r = 0; r < 4; r++) {
        int n = n0 + ty + r * 8;
        int k = k0 + tx;
        float x = tile[tx][ty + r * 8];
        __nv_bfloat16 h = __float2bfloat16(x);
        __nv_bfloat16 l = __float2bfloat16(x - __bfloat162float(h));
        bhi[(size_t)n * K + k] = h;
        blo[(size_t)n * K + k] = l;
    }
}

// ---------------- mma.sync split-bf16 GEMM (2 CTAs/SM, single-sync pipe) ------
#define GPITCH 80
#define GTSZ   (128 * GPITCH)
#define GSTG   (4 * GTSZ)
#define GEMM_SMEM_BYTES (2 * GSTG)     // 81920 -> 2 CTAs = 163840 <= 228KB

__global__ void __launch_bounds__(256, 2) gemm_mma_kernel(
    const __nv_bfloat16* __restrict__ Ahi, const __nv_bfloat16* __restrict__ Alo,
    const __nv_bfloat16* __restrict__ Bhi, const __nv_bfloat16* __restrict__ Blo,
    float* __restrict__ C, int Ntot)
{
    const uint32_t sb = smem_u32(dynsmem);
    const int t = threadIdx.x;
    const int wid = t >> 5, lane = t & 31;
    const int bm = blockIdx.y, bn = blockIdx.x;
    const int wm = (wid >> 2) * 64;
    const int wn = (wid & 3) * 32;

    const __nv_bfloat16* gsrc[4] = {
        Ahi + (size_t)(bm * 128) * KDIM,
        Alo + (size_t)(bm * 128) * KDIM,
        Bhi + (size_t)(bn * 128) * KDIM,
        Blo + (size_t)(bn * 128) * KDIM };

    const int lrow = t >> 1;
    const int lq   = (t & 1) * 2;

    auto load_chunk = [&](int c, int s) {
        uint32_t base = sb + s * GSTG + lrow * GPITCH + lq * 16;
#pragma unroll
        for (int tens = 0; tens < 4; tens++) {
            const __nv_bfloat16* src = gsrc[tens] + (size_t)lrow * KDIM + c * 32 + lq * 8;
            uint32_t d = base + tens * GTSZ;
            CP_ASYNC16(d, src);
            CP_ASYNC16(d + 16, src + 8);
        }
    };

    float acc[4][4][4];
#pragma unroll
    for (int a = 0; a < 4; a++)
#pragma unroll
        for (int b = 0; b < 4; b++)
#pragma unroll
            for (int c = 0; c < 4; c++) acc[a][b][c] = 0.f;

    const int NCH = KDIM / 32;

    load_chunk(0, 0);
    CP_COMMIT();

    for (int i = 0; i < NCH; i++) {
        const int s = i & 1;
        CP_WAIT(0);          // chunk i resident (issued one full compute ago)
        __syncthreads();     // also orders prev-iter readers of stage s^1
        if (i + 1 < NCH) {   // overlap next chunk's loads with compute below
            load_chunk(i + 1, s ^ 1);
            CP_COMMIT();
        }

        const uint32_t sA = sb + s * GSTG;
        const uint32_t sB = sA + 2 * GTSZ;

#pragma unroll
        for (int ks = 0; ks < 2; ks++) {
            const int k0b = ks * 32;
            uint32_t b_hi[2][4], b_lo[2][4];
#pragma unroll
            for (int p = 0; p < 2; p++) {
                uint32_t bd = sB + (uint32_t)(wn + p * 16 + ((lane >> 4) << 3) + (lane & 7)) * GPITCH
                            + k0b + (((lane >> 3) & 1) << 4);
                LDSM_X4(b_hi[p], bd);
                LDSM_X4(b_lo[p], bd + GTSZ);
            }
#pragma unroll
            for (int mt = 0; mt < 4; mt++) {
                uint32_t ah[4], al[4];
                uint32_t ad = sA + (uint32_t)(wm + mt * 16 + (lane & 15)) * GPITCH
                            + k0b + ((lane >> 4) << 4);
                LDSM_X4(ah, ad);
                LDSM_X4(al, ad + GTSZ);
                // product-major: 4 independent MMAs per product (stride-4 chains)
#pragma unroll
                for (int nt = 0; nt < 4; nt++) {
                    const int p = nt >> 1, hh = (nt & 1) * 2;
                    MMA16816(acc[mt][nt], ah, b_hi[p][hh], b_hi[p][hh + 1]);
                }
#pragma unroll
                for (int nt = 0; nt < 4; nt++) {
                    const int p = nt >> 1, hh = (nt & 1) * 2;
                    MMA16816(acc[mt][nt], ah, b_lo[p][hh], b_lo[p][hh + 1]);
                }
#pragma unroll
                for (int nt = 0; nt < 4; nt++) {
                    const int p = nt >> 1, hh = (nt & 1) * 2;
                    MMA16816(acc[mt][nt], al, b_hi[p][hh], b_hi[p][hh + 1]);
                }
            }
        }
    }

#pragma unroll
    for (int mt = 0; mt < 4; mt++)
#pragma unroll
        for (int nt = 0; nt < 4; nt++) {
            int row = bm * 128 + wm + mt * 16 + (lane >> 2);
            int col = bn * 128 + wn + nt * 8 + (lane & 3) * 2;
            float2 v0 = make_float2(acc[mt][nt][0], acc[mt][nt][1]);
            float2 v1 = make_float2(acc[mt][nt][2], acc[mt][nt][3]);
            *(float2*)(C + (size_t)row * Ntot + col)       = v0;
            *(float2*)(C + (size_t)(row + 8) * Ntot + col) = v1;
        }
}

// ---------------- RoPE (NeoX) + bf16 hi/lo split, natural [.,s,d] layout ------
__global__ void rope_split_kernel(const float* __restrict__ qkv,
                                  const int*   __restrict__ positions)
{
    int idx = blockIdx.x * 256 + threadIdx.x;
    int i  = idx & 63;
    int s  = (idx >> 6) & (S_LEN - 1);
    int r  = idx >> 17;          // b*40 + hh
    int hh = r % 40;
    int b  = r / 40;

    float pos = (float)positions[b * S_LEN + s];
    float ang = pos * g_invfreq[i];
    float sn, cs;
    sincosf(ang, &sn, &cs);

    if (hh < 32) {
        const float* src = qkv + ((size_t)(b * S_LEN + s)) * QKVN + hh * HD;
        float x1 = src[i], x2 = src[i + 64];
        float y1 = x1 * cs - x2 * sn;
        float y2 = x2 * cs + x1 * sn;
        size_t base = ((size_t)(b * NH + hh) * S_LEN + s) * HD;
        __nv_bfloat16 h1 = __float2bfloat16(y1);
        __nv_bfloat16 h2 = __float2bfloat16(y2);
        g_Qh[base + i]      = h1;
        g_Qh[base + i + 64] = h2;
        g_Ql[base + i]      = __float2bfloat16(y1 - __bfloat162float(h1));
        g_Ql[base + i + 64] = __float2bfloat16(y2 - __bfloat162float(h2));
    } else {
        int kh = hh - 32;
        const float* src = qkv + ((size_t)(b * S_LEN + s)) * QKVN + HID + kh * HD;
        float x1 = src[i], x2 = src[i + 64];
        float y1 = x1 * cs - x2 * sn;
        float y2 = x2 * cs + x1 * sn;
        size_t base = ((size_t)(b * NKV + kh) * S_LEN + s) * HD;
        __nv_bfloat16 h1 = __float2bfloat16(y1);
        __nv_bfloat16 h2 = __float2bfloat16(y2);
        g_Kh[base + i]      = h1;
        g_Kh[base + i + 64] = h2;
        g_Kl[base + i]      = __float2bfloat16(y1 - __bfloat162float(h1));
        g_Kl[base + i + 64] = __float2bfloat16(y2 - __bfloat162float(h2));
    }
}

// ---------------- V: [s][d] fp32 -> [d][s] bf16 hi/lo (tiled transpose) -------
__global__ void __launch_bounds__(256) v_split_kernel(const float* __restrict__ qkv)
{
    __shared__ float tile[32][33];
    int tx = threadIdx.x & 31, ty = threadIdx.x >> 5;   // 32 x 8
    int s0 = blockIdx.x * 32, d0 = blockIdx.y * 32;
    int slab = blockIdx.z;                               // b*NKV + kh
    int b = slab / NKV, kh = slab % NKV;

    const float* src = qkv + (size_t)(b * S_LEN) * QKVN + VOFF + kh * HD;
#pragma unroll
    for (int r = 0; r < 4; r++)
        tile[ty + r * 8][tx] = src[(size_t)(s0 + ty + r * 8) * QKVN + d0 + tx];
    __syncthreads();
#pragma unroll
    for (int r = 0; r < 4; r++) {
        int d = d0 + ty + r * 8;
        int s = s0 + tx;
        float x = tile[tx][ty + r * 8];
        __nv_bfloat16 h = __float2bfloat16(x);
        __nv_bfloat16 l = __float2bfloat16(x - __bfloat162float(h));
        size_t o = ((size_t)(b * NKV + kh) * HD + d) * S_LEN + s;
        g_Vh[o] = h;
        g_Vl[o] = l;
    }
}

// ---------------- mma.sync split-bf16 flash attention (single-sync pipe) ------
#define AQ_PITCH 272     // 256B row + 16B pad
#define AK_PITCH 272
#define AV_PITCH 144     // 128B row + 16B pad
#define SQ_BYTES (128 * AQ_PITCH)            // 34816
#define SK_BYTES (64  * AK_PITCH)            // 17408
#define SV_BYTES (128 * AV_PITCH)            // 18432
#define KV_STG   (2 * SK_BYTES + 2 * SV_BYTES)   // 71680 per stage
#define ATT_SMEM_BYTES (2 * SQ_BYTES + 2 * KV_STG)  // 212992

__global__ void __launch_bounds__(256, 1) attn_mma_kernel(
    __nv_bfloat16* __restrict__ Ohi, __nv_bfloat16* __restrict__ Olo)
{
    const int qt = blockIdx.x;      // 0..15 (128-row tiles)
    const int h  = blockIdx.y;
    const int b  = blockIdx.z;
    const int kh = h >> 2;

    const uint32_t sb  = smem_u32(dynsmem);
    const uint32_t sQh = sb;
    const uint32_t sQl = sQh + SQ_BYTES;
    const uint32_t sKV = sQl + SQ_BYTES;     // stage base: + s*KV_STG

    const int t = threadIdx.x;
    const int wid = t >> 5, lane = t & 31;
    const int wm = wid * 16;

    const __nv_bfloat16* kb0 = g_Kh + ((size_t)(b * NKV + kh) * S_LEN) * HD;
    const __nv_bfloat16* kb1 = g_Kl + ((size_t)(b * NKV + kh) * S_LEN) * HD;
    const __nv_bfloat16* vb0 = g_Vh + ((size_t)(b * NKV + kh) * HD) * S_LEN;
    const __nv_bfloat16* vb1 = g_Vl + ((size_t)(b * NKV + kh) * HD) * S_LEN;

    auto load_kv = [&](int kt, int s) {
        const uint32_t st = sKV + s * KV_STG;
#pragma unroll
        for (int u = 0; u < 4; u++) {
            int id = t + u * 256;            // 1024: 64 rows x 16 chunks
            int row = id >> 4, ch = id & 15;
            uint32_t d = row * AK_PITCH + ch * 16;
            const size_t go = (size_t)(kt * 64 + row) * HD + ch * 8;
            CP_ASYNC16(st + d, kb0 + go);
            CP_ASYNC16(st + SK_BYTES + d, kb1 + go);
        }
#pragma unroll
        for (int u = 0; u < 4; u++) {
            int id = t + u * 256;            // 1024: 128 rows x 8 chunks
            int row = id >> 3, ch = id & 7;
            uint32_t d = row * AV_PITCH + ch * 16;
            const size_t go = (size_t)row * S_LEN + kt * 64 + ch * 8;
            CP_ASYNC16(st + 2 * SK_BYTES + d, vb0 + go);
            CP_ASYNC16(st + 2 * SK_BYTES + SV_BYTES + d, vb1 + go);
        }
    };

    // ---- load Q tile (once) ----
    {
        const __nv_bfloat16* q0 = g_Qh + ((size_t)(b * NH + h) * S_LEN + qt * 128) * HD;
        const __nv_bfloat16* q1 = g_Ql + ((size_t)(b * NH + h) * S_LEN + qt * 128) * HD;
#pragma unroll
        for (int u = 0; u < 8; u++) {
            int id = t + u * 256;            // 2048 ids: 128 rows x 16 chunks
            int row = id >> 4, ch = id & 15;
            uint32_t d = row * AQ_PITCH + ch * 16;
            CP_ASYNC16(sQh + d, q0 + (size_t)row * HD + ch * 8);
            CP_ASYNC16(sQl + d, q1 + (size_t)row * HD + ch * 8);
        }
        CP_COMMIT();
    }

    float acc[16][4];
#pragma unroll
    for (int n = 0; n < 16; n++)
#pragma unroll
        for (int c = 0; c < 4; c++) acc[n][c] = 0.f;
    float m0 = -1e30f, m1 = -1e30f, l0 = 0.f, l1 = 0.f;

    const float SC = 0.08838834764831843f;
    const int nkt = 2 * qt + 2;

    load_kv(0, 0);
    CP_COMMIT();

    for (int kt = 0; kt < nkt; kt++) {
        const int s = kt & 1;
        CP_WAIT(0);          // tile kt (and Q on iter 0) resident
        __syncthreads();     // orders prev-iter readers of stage s^1
        if (kt + 1 < nkt) {  // overlap next tile's loads with compute
            load_kv(kt + 1, s ^ 1);
            CP_COMMIT();
        }

        const uint32_t sKh = sKV + s * KV_STG;
        const uint32_t sKl = sKh + SK_BYTES;
        const uint32_t sVh = sKh + 2 * SK_BYTES;
        const uint32_t sVl = sVh + SV_BYTES;

        // ---- scores: S = Q K^T (64 cols), 3-product split, product-major ----
        float sc4[8][4];
#pragma unroll
        for (int n = 0; n < 8; n++)
#pragma unroll
            for (int c = 0; c < 4; c++) sc4[n][c] = 0.f;

#pragma unroll
        for (int dc = 0; dc < 8; dc++) {
            const int k0b = dc * 32;
            uint32_t ah[4], al[4];
            uint32_t qa = sQh + (uint32_t)(wm + (lane & 15)) * AQ_PITCH + k0b + ((lane >> 4) << 4);
            LDSM_X4(ah, qa);
            LDSM_X4(al, qa + SQ_BYTES);
            uint32_t bh[4][4], bl[4][4];
#pragma unroll
            for (int p = 0; p < 4; p++) {
                uint32_t ka = sKh + (uint32_t)(p * 16 + ((lane >> 4) << 3) + (lane & 7)) * AK_PITCH
                            + k0b + (((lane >> 3) & 1) << 4);
                LDSM_X4(bh[p], ka);
                LDSM_X4(bl[p], ka + SK_BYTES);
            }
#pragma unroll
            for (int nt = 0; nt < 8; nt++) {
                const int p = nt >> 1, hh = (nt & 1) * 2;
                MMA16816(sc4[nt], ah, bh[p][hh], bh[p][hh + 1]);
            }
#pragma unroll
            for (int nt = 0; nt < 8; nt++) {
                const int p = nt >> 1, hh = (nt & 1) * 2;
                MMA16816(sc4[nt], ah, bl[p][hh], bl[p][hh + 1]);
            }
#pragma unroll
            for (int nt = 0; nt < 8; nt++) {
                const int p = nt >> 1, hh = (nt & 1) * 2;
                MMA16816(sc4[nt], al, bh[p][hh], bh[p][hh + 1]);
            }
        }

        // ---- scale + causal mask (only last two kt tiles need masking) ----
        if (kt >= 2 * qt) {
            const int gr0 = qt * 128 + wm + (lane >> 2);
#pragma unroll
            for (int nt = 0; nt < 8; nt++)
#pragma unroll
                for (int c = 0; c < 4; c++) {
                    int gc = kt * 64 + nt * 8 + ((lane & 3) << 1) + (c & 1);
                    int gr = gr0 + ((c >> 1) << 3);
                    sc4[nt][c] = (gc > gr) ? -1e30f : sc4[nt][c] * SC;
                }
        } else {
#pragma unroll
            for (int nt = 0; nt < 8; nt++)
#pragma unroll
                for (int c = 0; c < 4; c++) sc4[nt][c] *= SC;
        }

        // ---- online softmax (two rows per thread; quad shfl) ----
        float mt0 = -1e30f, mt1 = -1e30f;
#pragma unroll
        for (int nt = 0; nt < 8; nt++) {
            mt0 = fmaxf(mt0, fmaxf(sc4[nt][0], sc4[nt][1]));
            mt1 = fmaxf(mt1, fmaxf(sc4[nt][2], sc4[nt][3]));
        }
        mt0 = fmaxf(mt0, __shfl_xor_sync(0xffffffffu, mt0, 1));
        mt0 = fmaxf(mt0, __shfl_xor_sync(0xffffffffu, mt0, 2));
        mt1 = fmaxf(mt1, __shfl_xor_sync(0xffffffffu, mt1, 1));
        mt1 = fmaxf(mt1, __shfl_xor_sync(0xffffffffu, mt1, 2));
        float mn0 = fmaxf(m0, mt0), mn1 = fmaxf(m1, mt1);
        float es0 = __expf(m0 - mn0), es1 = __expf(m1 - mn1);
        float rs0 = 0.f, rs1 = 0.f;
#pragma unroll
        for (int nt = 0; nt < 8; nt++) {
            sc4[nt][0] = __expf(sc4[nt][0] - mn0);
            sc4[nt][1] = __expf(sc4[nt][1] - mn0);
            sc4[nt][2] = __expf(sc4[nt][2] - mn1);
            sc4[nt][3] = __expf(sc4[nt][3] - mn1);
            rs0 += sc4[nt][0] + sc4[nt][1];
            rs1 += sc4[nt][2] + sc4[nt][3];
        }
        rs0 += __shfl_xor_sync(0xffffffffu, rs0, 1);
        rs0 += __shfl_xor_sync(0xffffffffu, rs0, 2);
        rs1 += __shfl_xor_sync(0xffffffffu, rs1, 1);
        rs1 += __shfl_xor_sync(0xffffffffu, rs1, 2);
        l0 = l0 * es0 + rs0;  m0 = mn0;
        l1 = l1 * es1 + rs1;  m1 = mn1;
#pragma unroll
        for (int n = 0; n < 16; n++) {
            acc[n][0] *= es0;  acc[n][1] *= es0;
            acc[n][2] *= es1;  acc[n][3] *= es1;
        }

        // ---- PV: O += P V ; product-major within each dp ----
#pragma unroll
        for (int kc = 0; kc < 4; kc++) {
            uint32_t ph[4], pl[4];
            split2(sc4[2 * kc][0],     sc4[2 * kc][1],     ph[0], pl[0]);
            split2(sc4[2 * kc][2],     sc4[2 * kc][3],     ph[1], pl[1]);
            split2(sc4[2 * kc + 1][0], sc4[2 * kc + 1][1], ph[2], pl[2]);
            split2(sc4[2 * kc + 1][2], sc4[2 * kc + 1][3], ph[3], pl[3]);
#pragma unroll
            for (int dp = 0; dp < 8; dp++) {
                uint32_t vh4[4], vl4[4];
                uint32_t va = sVh + (uint32_t)(dp * 16 + ((lane >> 4) << 3) + (lane & 7)) * AV_PITCH
                            + kc * 32 + (((lane >> 3) & 1) << 4);
                LDSM_X4(vh4, va);
                LDSM_X4(vl4, va + SV_BYTES);
                const int n0 = dp * 2, n1 = dp * 2 + 1;
                MMA16816(acc[n0], ph, vh4[0], vh4[1]);
                MMA16816(acc[n1], ph, vh4[2], vh4[3]);
                MMA16816(acc[n0], ph, vl4[0], vl4[1]);
                MMA16816(acc[n1], ph, vl4[2], vl4[3]);
                MMA16816(acc[n0], pl, vh4[0], vh4[1]);
                MMA16816(acc[n1], pl, vh4[2], vh4[3]);
            }
        }
    }

    // ---- epilogue: normalize, split to bf16 hi/lo, write [b*S+s][h*128+d] ----
    const float inv0 = 1.0f / l0, inv1 = 1.0f / l1;
    const size_t row0 = (size_t)(b * S_LEN + qt * 128 + wm + (lane >> 2));
    const int colb = h * HD + ((lane & 3) << 1);
#pragma unroll
    for (int nt = 0; nt < 16; nt++) {
        uint32_t h0, lo0, h1, lo1;
        split2(acc[nt][0] * inv0, acc[nt][1] * inv0, h0, lo0);
        split2(acc[nt][2] * inv1, acc[nt][3] * inv1, h1, lo1);
        const size_t o0 = row0 * HID + colb + nt * 8;
        const size_t o1 = (row0 + 8) * HID + colb + nt * 8;
        *(uint32_t*)(Ohi + o0) = h0;
        *(uint32_t*)(Olo + o0) = lo0;
        *(uint32_t*)(Ohi + o1) = h1;
        *(uint32_t*)(Olo + o1) = lo1;
    }
}

// ---------------- launch ------------------------------------------------------
extern "C" void kernel_launch(void* const* d_in, const int* in_sizes, int n_in,
                              void* d_out, int out_size)
{
    const int*   positions = (const int*)  d_in[0];
    const float* hidden    = (const float*)d_in[1];
    const float* w_qkv     = (const float*)d_in[2];
    const float* w_o       = (const float*)d_in[3];
    float*       out       = (float*)d_out;

    static float* qkv_p;
    static __nv_bfloat16 *ahi, *alo, *bqh, *bql, *boh, *bol;
    static bool init_done = false;
    if (!init_done) {
        cudaGetSymbolAddress((void**)&qkv_p, g_qkv);
        cudaGetSymbolAddress((void**)&ahi, g_Ahi);
        cudaGetSymbolAddress((void**)&alo, g_Alo);
        cudaGetSymbolAddress((void**)&bqh, g_Bqh);
        cudaGetSymbolAddress((void**)&bql, g_Bql);
        cudaGetSymbolAddress((void**)&boh, g_Boh);
        cudaGetSymbolAddress((void**)&bol, g_Bol);
        cudaFuncSetAttribute(gemm_mma_kernel,
                             cudaFuncAttributeMaxDynamicSharedMemorySize, GEMM_SMEM_BYTES);
        cudaFuncSetAttribute(attn_mma_kernel,
                             cudaFuncAttributeMaxDynamicSharedMemorySize, ATT_SMEM_BYTES);
        init_done = true;
    }

    const int M = BATCH * S_LEN;   // 4096

    init_invfreq_kernel<<<1, 64>>>();

    // prep: split hidden, transpose+split weights
    split_a_kernel<<<(M * KDIM / 4 + 255) / 256, 256>>>(hidden, ahi, alo, M * KDIM / 4);
    transpose_split_kernel<<<dim3(QKVN / 32, KDIM / 32), 256>>>(w_qkv, bqh, bql, KDIM, QKVN);
    transpose_split_kernel<<<dim3(HID / 32, KDIM / 32), 256>>>(w_o, boh, bol, KDIM, HID);

    // qkv = hidden @ w_qkv
    gemm_mma_kernel<<<dim3(QKVN / 128, M / 128), 256, GEMM_SMEM_BYTES>>>(
        ahi, alo, bqh, bql, qkv_p, QKVN);

    // rope + split Q/K; transpose + split V
    rope_split_kernel<<<(BATCH * 40 * S_LEN * 64) / 256, 256>>>(qkv_p, positions);
    v_split_kernel<<<dim3(S_LEN / 32, HD / 32, BATCH * NKV), 256>>>(qkv_p);

    // flash attention (tensor cores); writes bf16 hi/lo directly into GEMM-A bufs
    attn_mma_kernel<<<dim3(S_LEN / 128, NH, BATCH), 256, ATT_SMEM_BYTES>>>(ahi, alo);

    // out = attn @ w_o
    gemm_mma_kernel<<<dim3(HID / 128, M / 128), 256, GEMM_SMEM_BYTES>>>(
        ahi, alo, boh, bol, out, HID);
}

// round 12
// speedup vs baseline: 3.5810x; 1.3003x over previous
#include <cuda_runtime.h>
#include <cuda_bf16.h>
#include <cuda_fp16.h>
#include <cstdint>
#include <math.h>

#define BATCH 2
#define S_LEN 2048
#define HID   4096
#define NH    32
#define NKV   8
#define HD    128
#define QKVN  6144          // Q 4096 | K 1024 | V 1024
#define VOFF  5120          // Q_SIZE + KV_SIZE
#define KDIM  4096          // GEMM K (reduction) for both projections

// ---------------- scratch (no allocation allowed -> device globals) ----------
__device__ float g_qkv [BATCH * S_LEN * QKVN];      // qkv projection output (fp32)
__device__ float g_invfreq[64];

// fp16 split operands for the tensor-core GEMMs (A exact as hi+lo; B hi only)
__device__ __half g_Ahi [4096 * 4096];              // A hi (hidden; then attn out)
__device__ __half g_Alo [4096 * 4096];              // A lo
__device__ __half g_Bqh [QKVN * 4096];              // w_qkv^T fp16  [N=6144][K=4096]
__device__ __half g_Boh [4096 * 4096];              // w_o^T  fp16   [N=4096][K=4096]

// bf16 split attention operands (bf16 x3 path, unchanged)
__device__ __nv_bfloat16 g_Qh [BATCH * NH  * S_LEN * HD];  // [b][h][s][d]
__device__ __nv_bfloat16 g_Ql [BATCH * NH  * S_LEN * HD];
__device__ __nv_bfloat16 g_Kh [BATCH * NKV * S_LEN * HD];  // [b][kh][s][d]
__device__ __nv_bfloat16 g_Kl [BATCH * NKV * S_LEN * HD];
__device__ __nv_bfloat16 g_Vh [BATCH * NKV * HD * S_LEN];  // [b][kh][d][s]
__device__ __nv_bfloat16 g_Vl [BATCH * NKV * HD * S_LEN];

// ================= helpers ====================================================
__device__ __forceinline__ uint32_t smem_u32(const void* p) {
    uint32_t a;
    asm("{ .reg .u64 t; cvta.to.shared.u64 t, %1; cvt.u32.u64 %0, t; }" : "=r"(a) : "l"(p));
    return a;
}

#define LDSM_X4(r, addr) \
    asm volatile("ldmatrix.sync.aligned.m8n8.x4.shared.b16 {%0,%1,%2,%3}, [%4];" \
        : "=r"((r)[0]), "=r"((r)[1]), "=r"((r)[2]), "=r"((r)[3]) : "r"(addr))

// bf16 MMA (attention)
#define MMA16816(c, a, b0, b1) \
    asm volatile("mma.sync.aligned.m16n8k16.row.col.f32.bf16.bf16.f32 " \
        "{%0,%1,%2,%3}, {%4,%5,%6,%7}, {%8,%9}, {%0,%1,%2,%3};" \
        : "+f"((c)[0]), "+f"((c)[1]), "+f"((c)[2]), "+f"((c)[3]) \
        : "r"((a)[0]), "r"((a)[1]), "r"((a)[2]), "r"((a)[3]), "r"(b0), "r"(b1))

// fp16 MMA (projection GEMMs)
#define MMAF16(c, a, b0, b1) \
    asm volatile("mma.sync.aligned.m16n8k16.row.col.f32.f16.f16.f32 " \
        "{%0,%1,%2,%3}, {%4,%5,%6,%7}, {%8,%9}, {%0,%1,%2,%3};" \
        : "+f"((c)[0]), "+f"((c)[1]), "+f"((c)[2]), "+f"((c)[3]) \
        : "r"((a)[0]), "r"((a)[1]), "r"((a)[2]), "r"((a)[3]), "r"(b0), "r"(b1))

#define CP_ASYNC16(dst, src) \
    asm volatile("cp.async.cg.shared.global [%0], [%1], 16;" :: "r"(dst), "l"(src))
#define CP_COMMIT() asm volatile("cp.async.commit_group;" ::: "memory")
#define CP_WAIT(n)  asm volatile("cp.async.wait_group %0;" :: "n"(n) : "memory")

__device__ __forceinline__ void split2(float a, float b, uint32_t& hi, uint32_t& lo) {
    __nv_bfloat16 ha = __float2bfloat16(a), hb = __float2bfloat16(b);
    __nv_bfloat16 la = __float2bfloat16(a - __bfloat162float(ha));
    __nv_bfloat16 lb = __float2bfloat16(b - __bfloat162float(hb));
    __nv_bfloat162 H = __halves2bfloat162(ha, hb);
    __nv_bfloat162 L = __halves2bfloat162(la, lb);
    hi = *(uint32_t*)&H;  lo = *(uint32_t*)&L;
}

__device__ __forceinline__ void split2h(float a, float b, uint32_t& hi, uint32_t& lo) {
    __half ha = __float2half_rn(a), hb = __float2half_rn(b);
    __half la = __float2half_rn(a - __half2float(ha));
    __half lb = __float2half_rn(b - __half2float(hb));
    __half2 H = __halves2half2(ha, hb);
    __half2 L = __halves2half2(la, lb);
    hi = *(uint32_t*)&H;  lo = *(uint32_t*)&L;
}

extern __shared__ char dynsmem[];

// ---------------- inv_freq table ---------------------------------------------
__global__ void init_invfreq_kernel() {
    int i = threadIdx.x;
    if (i < 64) {
        const float LOG2_10000 = 13.28771237954945f;
        g_invfreq[i] = exp2f(-((float)(2 * i) / 128.0f) * LOG2_10000);
    }
}

// ---------------- fp32 -> fp16 hi/lo split (elementwise, float4) --------------
__global__ void __launch_bounds__(256) split_a_kernel(
    const float* __restrict__ X, __half* __restrict__ hi,
    __half* __restrict__ lo, int n4)
{
    int i = blockIdx.x * 256 + threadIdx.x;
    if (i >= n4) return;
    float4 v = ((const float4*)X)[i];
    uint32_t h0, l0, h1, l1;
    split2h(v.x, v.y, h0, l0);
    split2h(v.z, v.w, h1, l1);
    ((uint32_t*)hi)[i * 2]     = h0;
    ((uint32_t*)hi)[i * 2 + 1] = h1;
    ((uint32_t*)lo)[i * 2]     = l0;
    ((uint32_t*)lo)[i * 2 + 1] = l1;
}

// ---------------- W[K,N] fp32 -> Bt[N,K] fp16 (tiled transpose, hi only) ------
__global__ void __launch_bounds__(256) transpose_split_kernel(
    const float* __restrict__ W, __half* __restrict__ bhi, int K, int N)
{
    __shared__ float tile[32][33];
    int tx = threadIdx.x & 31, ty = threadIdx.x >> 5;   // 32 x 8
    int k0 = blockIdx.y * 32, n0 = blockIdx.x * 32;
#pragma unroll
    for (int r = 0; r < 4; r++)
        tile[ty + r * 8][tx] = W[(size_t)(k0 + ty + r * 8) * N + n0 + tx];
    __syncthreads();
#pragma unroll
    for (int r = 0; r < 4; r++) {
        int n = n0 + ty + r * 8;
        int k = k0 + tx;
        bhi[(size_t)n * K + k] = __float2half_rn(tile[tx][ty + r * 8]);
    }
}

// ---------------- mma.sync fp16 2-product GEMM (3-stage, 2 CTAs/SM) -----------
// C = A @ W ; A exact as fp16 (Ah + Al), B as single fp16 Bh.
// C = Ah*Bh + Al*Bh  (dropped A*(B-Bh) ~ 1.4e-4 relative)
#define GPITCH 80
#define GTSZ   (128 * GPITCH)          // 10240
#define GSTG   (3 * GTSZ)              // 30720 per stage (Ah | Al | Bh)
#define GEMM_SMEM_BYTES (3 * GSTG)     // 92160 -> 2 CTAs = 184320 <= 228KB

__global__ void __launch_bounds__(256, 2) gemm_mma_kernel(
    const __half* __restrict__ Ahi, const __half* __restrict__ Alo,
    const __half* __restrict__ Bh,
    float* __restrict__ C, int Ntot)
{
    const uint32_t sb = smem_u32(dynsmem);
    const int t = threadIdx.x;
    const int wid = t >> 5, lane = t & 31;
    const int bm = blockIdx.y, bn = blockIdx.x;
    const int wm = (wid >> 2) * 64;
    const int wn = (wid & 3) * 32;

    const __half* gsrc[3] = {
        Ahi + (size_t)(bm * 128) * KDIM,
        Alo + (size_t)(bm * 128) * KDIM,
        Bh  + (size_t)(bn * 128) * KDIM };

    const int lrow = t >> 1;
    const int lq   = (t & 1) * 2;

    auto load_chunk = [&](int c, int s) {
        uint32_t base = sb + s * GSTG + lrow * GPITCH + lq * 16;
#pragma unroll
        for (int tens = 0; tens < 3; tens++) {
            const __half* src = gsrc[tens] + (size_t)lrow * KDIM + c * 32 + lq * 8;
            uint32_t d = base + tens * GTSZ;
            CP_ASYNC16(d, src);
            CP_ASYNC16(d + 16, src + 8);
        }
    };

    float acc[4][4][4];
#pragma unroll
    for (int a = 0; a < 4; a++)
#pragma unroll
        for (int b = 0; b < 4; b++)
#pragma unroll
            for (int c = 0; c < 4; c++) acc[a][b][c] = 0.f;

    const int NCH = KDIM / 32;   // 128 chunks

    load_chunk(0, 0);
    CP_COMMIT();
    load_chunk(1, 1);
    CP_COMMIT();

    for (int i = 0; i < NCH; i++) {
        const int s = i % 3;
        if (i + 1 < NCH) CP_WAIT(1); else CP_WAIT(0);   // chunk i resident
        __syncthreads();          // all warps done with stage (i+2)%3 (chunk i-1)
        if (i + 2 < NCH) {        // overlap chunk i+2 loads with compute on i
            load_chunk(i + 2, (i + 2) % 3);
            CP_COMMIT();
        }

        const uint32_t sA  = sb + s * GSTG;
        const uint32_t sAl = sA + GTSZ;
        const uint32_t sB  = sA + 2 * GTSZ;

#pragma unroll
        for (int ks = 0; ks < 2; ks++) {
            const int k0b = ks * 32;
            uint32_t b_hi[2][4];
#pragma unroll
            for (int p = 0; p < 2; p++) {
                uint32_t bd = sB + (uint32_t)(wn + p * 16 + ((lane >> 4) << 3) + (lane & 7)) * GPITCH
                            + k0b + (((lane >> 3) & 1) << 4);
                LDSM_X4(b_hi[p], bd);
            }
#pragma unroll
            for (int mt = 0; mt < 4; mt++) {
                uint32_t ah[4], al[4];
                uint32_t ad = sA + (uint32_t)(wm + mt * 16 + (lane & 15)) * GPITCH
                            + k0b + ((lane >> 4) << 4);
                LDSM_X4(ah, ad);
                LDSM_X4(al, ad + GTSZ);
#pragma unroll
                for (int nt = 0; nt < 4; nt++) {
                    const int p = nt >> 1, hh = (nt & 1) * 2;
                    MMAF16(acc[mt][nt], ah, b_hi[p][hh], b_hi[p][hh + 1]);
                }
#pragma unroll
                for (int nt = 0; nt < 4; nt++) {
                    const int p = nt >> 1, hh = (nt & 1) * 2;
                    MMAF16(acc[mt][nt], al, b_hi[p][hh], b_hi[p][hh + 1]);
                }
            }
        }
    }

#pragma unroll
    for (int mt = 0; mt < 4; mt++)
#pragma unroll
        for (int nt = 0; nt < 4; nt++) {
            int row = bm * 128 + wm + mt * 16 + (lane >> 2);
            int col = bn * 128 + wn + nt * 8 + (lane & 3) * 2;
            float2 v0 = make_float2(acc[mt][nt][0], acc[mt][nt][1]);
            float2 v1 = make_float2(acc[mt][nt][2], acc[mt][nt][3]);
            *(float2*)(C + (size_t)row * Ntot + col)       = v0;
            *(float2*)(C + (size_t)(row + 8) * Ntot + col) = v1;
        }
}

// ---------------- RoPE (NeoX) + bf16 hi/lo split, natural [.,s,d] layout ------
__global__ void rope_split_kernel(const float* __restrict__ qkv,
                                  const int*   __restrict__ positions)
{
    int idx = blockIdx.x * 256 + threadIdx.x;
    int i  = idx & 63;
    int s  = (idx >> 6) & (S_LEN - 1);
    int r  = idx >> 17;          // b*40 + hh
    int hh = r % 40;
    int b  = r / 40;

    float pos = (float)positions[b * S_LEN + s];
    float ang = pos * g_invfreq[i];
    float sn, cs;
    sincosf(ang, &sn, &cs);

    if (hh < 32) {
        const float* src = qkv + ((size_t)(b * S_LEN + s)) * QKVN + hh * HD;
        float x1 = src[i], x2 = src[i + 64];
        float y1 = x1 * cs - x2 * sn;
        float y2 = x2 * cs + x1 * sn;
        size_t base = ((size_t)(b * NH + hh) * S_LEN + s) * HD;
        __nv_bfloat16 h1 = __float2bfloat16(y1);
        __nv_bfloat16 h2 = __float2bfloat16(y2);
        g_Qh[base + i]      = h1;
        g_Qh[base + i + 64] = h2;
        g_Ql[base + i]      = __float2bfloat16(y1 - __bfloat162float(h1));
        g_Ql[base + i + 64] = __float2bfloat16(y2 - __bfloat162float(h2));
    } else {
        int kh = hh - 32;
        const float* src = qkv + ((size_t)(b * S_LEN + s)) * QKVN + HID + kh * HD;
        float x1 = src[i], x2 = src[i + 64];
        float y1 = x1 * cs - x2 * sn;
        float y2 = x2 * cs + x1 * sn;
        size_t base = ((size_t)(b * NKV + kh) * S_LEN + s) * HD;
        __nv_bfloat16 h1 = __float2bfloat16(y1);
        __nv_bfloat16 h2 = __float2bfloat16(y2);
        g_Kh[base + i]      = h1;
        g_Kh[base + i + 64] = h2;
        g_Kl[base + i]      = __float2bfloat16(y1 - __bfloat162float(h1));
        g_Kl[base + i + 64] = __float2bfloat16(y2 - __bfloat162float(h2));
    }
}

// ---------------- V: [s][d] fp32 -> [d][s] bf16 hi/lo (tiled transpose) -------
__global__ void __launch_bounds__(256) v_split_kernel(const float* __restrict__ qkv)
{
    __shared__ float tile[32][33];
    int tx = threadIdx.x & 31, ty = threadIdx.x >> 5;   // 32 x 8
    int s0 = blockIdx.x * 32, d0 = blockIdx.y * 32;
    int slab = blockIdx.z;                               // b*NKV + kh
    int b = slab / NKV, kh = slab % NKV;

    const float* src = qkv + (size_t)(b * S_LEN) * QKVN + VOFF + kh * HD;
#pragma unroll
    for (int r = 0; r < 4; r++)
        tile[ty + r * 8][tx] = src[(size_t)(s0 + ty + r * 8) * QKVN + d0 + tx];
    __syncthreads();
#pragma unroll
    for (int r = 0; r < 4; r++) {
        int d = d0 + ty + r * 8;
        int s = s0 + tx;
        float x = tile[tx][ty + r * 8];
        __nv_bfloat16 h = __float2bfloat16(x);
        __nv_bfloat16 l = __float2bfloat16(x - __bfloat162float(h));
        size_t o = ((size_t)(b * NKV + kh) * HD + d) * S_LEN + s;
        g_Vh[o] = h;
        g_Vl[o] = l;
    }
}

// ---------------- mma.sync split-bf16 flash attention (single-sync pipe) ------
#define AQ_PITCH 272     // 256B row + 16B pad
#define AK_PITCH 272
#define AV_PITCH 144     // 128B row + 16B pad
#define SQ_BYTES (128 * AQ_PITCH)            // 34816
#define SK_BYTES (64  * AK_PITCH)            // 17408
#define SV_BYTES (128 * AV_PITCH)            // 18432
#define KV_STG   (2 * SK_BYTES + 2 * SV_BYTES)   // 71680 per stage
#define ATT_SMEM_BYTES (2 * SQ_BYTES + 2 * KV_STG)  // 212992

__global__ void __launch_bounds__(256, 1) attn_mma_kernel(
    __half* __restrict__ Ohi, __half* __restrict__ Olo)
{
    const int qt = blockIdx.x;      // 0..15 (128-row tiles)
    const int h  = blockIdx.y;
    const int b  = blockIdx.z;
    const int kh = h >> 2;

    const uint32_t sb  = smem_u32(dynsmem);
    const uint32_t sQh = sb;
    const uint32_t sQl = sQh + SQ_BYTES;
    const uint32_t sKV = sQl + SQ_BYTES;     // stage base: + s*KV_STG

    const int t = threadIdx.x;
    const int wid = t >> 5, lane = t & 31;
    const int wm = wid * 16;

    const __nv_bfloat16* kb0 = g_Kh + ((size_t)(b * NKV + kh) * S_LEN) * HD;
    const __nv_bfloat16* kb1 = g_Kl + ((size_t)(b * NKV + kh) * S_LEN) * HD;
    const __nv_bfloat16* vb0 = g_Vh + ((size_t)(b * NKV + kh) * HD) * S_LEN;
    const __nv_bfloat16* vb1 = g_Vl + ((size_t)(b * NKV + kh) * HD) * S_LEN;

    auto load_kv = [&](int kt, int s) {
        const uint32_t st = sKV + s * KV_STG;
#pragma unroll
        for (int u = 0; u < 4; u++) {
            int id = t + u * 256;            // 1024: 64 rows x 16 chunks
            int row = id >> 4, ch = id & 15;
            uint32_t d = row * AK_PITCH + ch * 16;
            const size_t go = (size_t)(kt * 64 + row) * HD + ch * 8;
            CP_ASYNC16(st + d, kb0 + go);
            CP_ASYNC16(st + SK_BYTES + d, kb1 + go);
        }
#pragma unroll
        for (int u = 0; u < 4; u++) {
            int id = t + u * 256;            // 1024: 128 rows x 8 chunks
            int row = id >> 3, ch = id & 7;
            uint32_t d = row * AV_PITCH + ch * 16;
            const size_t go = (size_t)row * S_LEN + kt * 64 + ch * 8;
            CP_ASYNC16(st + 2 * SK_BYTES + d, vb0 + go);
            CP_ASYNC16(st + 2 * SK_BYTES + SV_BYTES + d, vb1 + go);
        }
    };

    // ---- load Q tile (once) ----
    {
        const __nv_bfloat16* q0 = g_Qh + ((size_t)(b * NH + h) * S_LEN + qt * 128) * HD;
        const __nv_bfloat16* q1 = g_Ql + ((size_t)(b * NH + h) * S_LEN + qt * 128) * HD;
#pragma unroll
        for (int u = 0; u < 8; u++) {
            int id = t + u * 256;            // 2048 ids: 128 rows x 16 chunks
            int row = id >> 4, ch = id & 15;
            uint32_t d = row * AQ_PITCH + ch * 16;
            CP_ASYNC16(sQh + d, q0 + (size_t)row * HD + ch * 8);
            CP_ASYNC16(sQl + d, q1 + (size_t)row * HD + ch * 8);
        }
        CP_COMMIT();
    }

    float acc[16][4];
#pragma unroll
    for (int n = 0; n < 16; n++)
#pragma unroll
        for (int c = 0; c < 4; c++) acc[n][c] = 0.f;
    float m0 = -1e30f, m1 = -1e30f, l0 = 0.f, l1 = 0.f;

    const float SC = 0.08838834764831843f;
    const int nkt = 2 * qt + 2;

    load_kv(0, 0);
    CP_COMMIT();

    for (int kt = 0; kt < nkt; kt++) {
        const int s = kt & 1;
        CP_WAIT(0);          // tile kt (and Q on iter 0) resident
        __syncthreads();     // orders prev-iter readers of stage s^1
        if (kt + 1 < nkt) {  // overlap next tile's loads with compute
            load_kv(kt + 1, s ^ 1);
            CP_COMMIT();
        }

        const uint32_t sKh = sKV + s * KV_STG;
        const uint32_t sKl = sKh + SK_BYTES;
        const uint32_t sVh = sKh + 2 * SK_BYTES;
        const uint32_t sVl = sVh + SV_BYTES;

        // ---- scores: S = Q K^T (64 cols), 3-product split, product-major ----
        float sc4[8][4];
#pragma unroll
        for (int n = 0; n < 8; n++)
#pragma unroll
            for (int c = 0; c < 4; c++) sc4[n][c] = 0.f;

#pragma unroll
        for (int dc = 0; dc < 8; dc++) {
            const int k0b = dc * 32;
            uint32_t ah[4], al[4];
            uint32_t qa = sQh + (uint32_t)(wm + (lane & 15)) * AQ_PITCH + k0b + ((lane >> 4) << 4);
            LDSM_X4(ah, qa);
            LDSM_X4(al, qa + SQ_BYTES);
            uint32_t bh[4][4], bl[4][4];
#pragma unroll
            for (int p = 0; p < 4; p++) {
                uint32_t ka = sKh + (uint32_t)(p * 16 + ((lane >> 4) << 3) + (lane & 7)) * AK_PITCH
                            + k0b + (((lane >> 3) & 1) << 4);
                LDSM_X4(bh[p], ka);
                LDSM_X4(bl[p], ka + SK_BYTES);
            }
#pragma unroll
            for (int nt = 0; nt < 8; nt++) {
                const int p = nt >> 1, hh = (nt & 1) * 2;
                MMA16816(sc4[nt], ah, bh[p][hh], bh[p][hh + 1]);
            }
#pragma unroll
            for (int nt = 0; nt < 8; nt++) {
                const int p = nt >> 1, hh = (nt & 1) * 2;
                MMA16816(sc4[nt], ah, bl[p][hh], bl[p][hh + 1]);
            }
#pragma unroll
            for (int nt = 0; nt < 8; nt++) {
                const int p = nt >> 1, hh = (nt & 1) * 2;
                MMA16816(sc4[nt], al, bh[p][hh], bh[p][hh + 1]);
            }
        }

        // ---- scale + causal mask (only last two kt tiles need masking) ----
        if (kt >= 2 * qt) {
            const int gr0 = qt * 128 + wm + (lane >> 2);
#pragma unroll
            for (int nt = 0; nt < 8; nt++)
#pragma unroll
                for (int c = 0; c < 4; c++) {
                    int gc = kt * 64 + nt * 8 + ((lane & 3) << 1) + (c & 1);
                    int gr = gr0 + ((c >> 1) << 3);
                    sc4[nt][c] = (gc > gr) ? -1e30f : sc4[nt][c] * SC;
                }
        } else {
#pragma unroll
            for (int nt = 0; nt < 8; nt++)
#pragma unroll
                for (int c = 0; c < 4; c++) sc4[nt][c] *= SC;
        }

        // ---- online softmax (two rows per thread; quad shfl) ----
        float mt0 = -1e30f, mt1 = -1e30f;
#pragma unroll
        for (int nt = 0; nt < 8; nt++) {
            mt0 = fmaxf(mt0, fmaxf(sc4[nt][0], sc4[nt][1]));
            mt1 = fmaxf(mt1, fmaxf(sc4[nt][2], sc4[nt][3]));
        }
        mt0 = fmaxf(mt0, __shfl_xor_sync(0xffffffffu, mt0, 1));
        mt0 = fmaxf(mt0, __shfl_xor_sync(0xffffffffu, mt0, 2));
        mt1 = fmaxf(mt1, __shfl_xor_sync(0xffffffffu, mt1, 1));
        mt1 = fmaxf(mt1, __shfl_xor_sync(0xffffffffu, mt1, 2));
        float mn0 = fmaxf(m0, mt0), mn1 = fmaxf(m1, mt1);
        float es0 = __expf(m0 - mn0), es1 = __expf(m1 - mn1);
        float rs0 = 0.f, rs1 = 0.f;
#pragma unroll
        for (int nt = 0; nt < 8; nt++) {
            sc4[nt][0] = __expf(sc4[nt][0] - mn0);
            sc4[nt][1] = __expf(sc4[nt][1] - mn0);
            sc4[nt][2] = __expf(sc4[nt][2] - mn1);
            sc4[nt][3] = __expf(sc4[nt][3] - mn1);
            rs0 += sc4[nt][0] + sc4[nt][1];
            rs1 += sc4[nt][2] + sc4[nt][3];
        }
        rs0 += __shfl_xor_sync(0xffffffffu, rs0, 1);
        rs0 += __shfl_xor_sync(0xffffffffu, rs0, 2);
        rs1 += __shfl_xor_sync(0xffffffffu, rs1, 1);
        rs1 += __shfl_xor_sync(0xffffffffu, rs1, 2);
        l0 = l0 * es0 + rs0;  m0 = mn0;
        l1 = l1 * es1 + rs1;  m1 = mn1;
#pragma unroll
        for (int n = 0; n < 16; n++) {
            acc[n][0] *= es0;  acc[n][1] *= es0;
            acc[n][2] *= es1;  acc[n][3] *= es1;
        }

        // ---- PV: O += P V ; product-major within each dp ----
#pragma unroll
        for (int kc = 0; kc < 4; kc++) {
            uint32_t ph[4], pl[4];
            split2(sc4[2 * kc][0],     sc4[2 * kc][1],     ph[0], pl[0]);
            split2(sc4[2 * kc][2],     sc4[2 * kc][3],     ph[1], pl[1]);
            split2(sc4[2 * kc + 1][0], sc4[2 * kc + 1][1], ph[2], pl[2]);
            split2(sc4[2 * kc + 1][2], sc4[2 * kc + 1][3], ph[3], pl[3]);
#pragma unroll
            for (int dp = 0; dp < 8; dp++) {
                uint32_t vh4[4], vl4[4];
                uint32_t va = sVh + (uint32_t)(dp * 16 + ((lane >> 4) << 3) + (lane & 7)) * AV_PITCH
                            + kc * 32 + (((lane >> 3) & 1) << 4);
                LDSM_X4(vh4, va);
                LDSM_X4(vl4, va + SV_BYTES);
                const int n0 = dp * 2, n1 = dp * 2 + 1;
                MMA16816(acc[n0], ph, vh4[0], vh4[1]);
                MMA16816(acc[n1], ph, vh4[2], vh4[3]);
                MMA16816(acc[n0], ph, vl4[0], vl4[1]);
                MMA16816(acc[n1], ph, vl4[2], vl4[3]);
                MMA16816(acc[n0], pl, vh4[0], vh4[1]);
                MMA16816(acc[n1], pl, vh4[2], vh4[3]);
            }
        }
    }

    // ---- epilogue: normalize, split to fp16 hi/lo, write [b*S+s][h*128+d] ----
    const float inv0 = 1.0f / l0, inv1 = 1.0f / l1;
    const size_t row0 = (size_t)(b * S_LEN + qt * 128 + wm + (lane >> 2));
    const int colb = h * HD + ((lane & 3) << 1);
#pragma unroll
    for (int nt = 0; nt < 16; nt++) {
        uint32_t h0, lo0, h1, lo1;
        split2h(acc[nt][0] * inv0, acc[nt][1] * inv0, h0, lo0);
        split2h(acc[nt][2] * inv1, acc[nt][3] * inv1, h1, lo1);
        const size_t o0 = row0 * HID + colb + nt * 8;
        const size_t o1 = (row0 + 8) * HID + colb + nt * 8;
        *(uint32_t*)(Ohi + o0) = h0;
        *(uint32_t*)(Olo + o0) = lo0;
        *(uint32_t*)(Ohi + o1) = h1;
        *(uint32_t*)(Olo + o1) = lo1;
    }
}

// ---------------- launch ------------------------------------------------------
extern "C" void kernel_launch(void* const* d_in, const int* in_sizes, int n_in,
                              void* d_out, int out_size)
{
    const int*   positions = (const int*)  d_in[0];
    const float* hidden    = (const float*)d_in[1];
    const float* w_qkv     = (const float*)d_in[2];
    const float* w_o       = (const float*)d_in[3];
    float*       out       = (float*)d_out;

    static float* qkv_p;
    static __half *ahi, *alo, *bqh, *boh;
    static bool init_done = false;
    if (!init_done) {
        cudaGetSymbolAddress((void**)&qkv_p, g_qkv);
        cudaGetSymbolAddress((void**)&ahi, g_Ahi);
        cudaGetSymbolAddress((void**)&alo, g_Alo);
        cudaGetSymbolAddress((void**)&bqh, g_Bqh);
        cudaGetSymbolAddress((void**)&boh, g_Boh);
        cudaFuncSetAttribute(gemm_mma_kernel,
                             cudaFuncAttributeMaxDynamicSharedMemorySize, GEMM_SMEM_BYTES);
        cudaFuncSetAttribute(attn_mma_kernel,
                             cudaFuncAttributeMaxDynamicSharedMemorySize, ATT_SMEM_BYTES);
        init_done = true;
    }

    const int M = BATCH * S_LEN;   // 4096

    init_invfreq_kernel<<<1, 64>>>();

    // prep: split hidden (fp16 hi/lo), transpose weights (fp16 hi)
    split_a_kernel<<<(M * KDIM / 4 + 255) / 256, 256>>>(hidden, ahi, alo, M * KDIM / 4);
    transpose_split_kernel<<<dim3(QKVN / 32, KDIM / 32), 256>>>(w_qkv, bqh, KDIM, QKVN);
    transpose_split_kernel<<<dim3(HID / 32, KDIM / 32), 256>>>(w_o, boh, KDIM, HID);

    // qkv = hidden @ w_qkv  (fp16 2-product)
    gemm_mma_kernel<<<dim3(QKVN / 128, M / 128), 256, GEMM_SMEM_BYTES>>>(
        ahi, alo, bqh, qkv_p, QKVN);

    // rope + split Q/K (bf16); transpose + split V (bf16)
    rope_split_kernel<<<(BATCH * 40 * S_LEN * 64) / 256, 256>>>(qkv_p, positions);
    v_split_kernel<<<dim3(S_LEN / 32, HD / 32, BATCH * NKV), 256>>>(qkv_p);

    // flash attention (bf16 x3); writes fp16 hi/lo directly into GEMM-A bufs
    attn_mma_kernel<<<dim3(S_LEN / 128, NH, BATCH), 256, ATT_SMEM_BYTES>>>(ahi, alo);

    // out = attn @ w_o  (fp16 2-product)
    gemm_mma_kernel<<<dim3(HID / 128, M / 128), 256, GEMM_SMEM_BYTES>>>(
        ahi, alo, boh, out, HID);
}